// round 8
// baseline (speedup 1.0000x reference)
#include <cuda_runtime.h>
#include <cuda_fp16.h>
#include <math.h>
#include <stddef.h>
#include <stdint.h>

// ---------------------------------------------------------------------------
// Problem dims
// ---------------------------------------------------------------------------
#define BATCH 4
#define T 1024
#define H 1024
#define NH 16
#define HD 64
#define CD 768
#define SC 77
#define FF 4096
#define BT (BATCH * T)

// ---------------------------------------------------------------------------
// Scratch
// ---------------------------------------------------------------------------
__device__ float g_x[BT * H];           // residual stream (fp32)
__device__ __half g_ln_h[BT * H];       // LN output (fp16)
__device__ __half g_qkv_h[BT * 3 * H];  // fused QKV (self) / also holds cross Q via g_q_h
__device__ __half g_q_h[BT * H];        // cross-attn Q
__device__ __half g_ckv_h[BATCH * SC * 2 * H]; // fused cross K/V
__device__ __half g_attn_h[BT * H];
__device__ __half g_hid_h[BT * FF];
__device__ __half g_ctx_h[BATCH * SC * CD];
// transposed fp16 weights, [N,K] row-major. Q,K,V contiguous; CK,CV contiguous.
#define WT_Q   0
#define WT_K   (WT_Q + H * H)
#define WT_V   (WT_K + H * H)
#define WT_O   (WT_V + H * H)
#define WT_CQ  (WT_O + H * H)
#define WT_CO  (WT_CQ + H * H)
#define WT_CK  (WT_CO + H * H)
#define WT_CV  (WT_CK + H * CD)
#define WT_F1A (WT_CV + H * CD)
#define WT_F1B (WT_F1A + FF * H)
#define WT_F2A (WT_F1B + H * FF)
#define WT_F2B (WT_F2A + FF * H)
#define WT_TOTAL (WT_F2B + H * FF)
__device__ __half g_wt[WT_TOTAL];

// ---------------------------------------------------------------------------
// Utility
// ---------------------------------------------------------------------------
__device__ __forceinline__ float warpSum(float v) {
#pragma unroll
    for (int o = 16; o; o >>= 1) v += __shfl_xor_sync(0xffffffffu, v, o);
    return v;
}
__device__ __forceinline__ uint32_t smem_u32(const void* p) {
    uint32_t a;
    asm("{ .reg .u64 t; cvta.to.shared.u64 t, %1; cvt.u32.u64 %0, t; }" : "=r"(a) : "l"(p));
    return a;
}
__device__ __forceinline__ void cp16(uint32_t saddr, const void* g, int srcBytes) {
    asm volatile("cp.async.cg.shared.global [%0], [%1], 16, %2;"
                 :: "r"(saddr), "l"(g), "r"(srcBytes) : "memory");
}
#define CP_COMMIT() asm volatile("cp.async.commit_group;" ::: "memory")
#define CP_WAIT1()  asm volatile("cp.async.wait_group 1;" ::: "memory")
#define CP_WAIT0()  asm volatile("cp.async.wait_group 0;" ::: "memory")

__device__ __forceinline__ void mma_f16(float* c, const uint32_t* a, const uint32_t* b) {
    asm volatile(
        "mma.sync.aligned.m16n8k16.row.col.f32.f16.f16.f32 "
        "{%0,%1,%2,%3}, {%4,%5,%6,%7}, {%8,%9}, {%0,%1,%2,%3};"
        : "+f"(c[0]), "+f"(c[1]), "+f"(c[2]), "+f"(c[3])
        : "r"(a[0]), "r"(a[1]), "r"(a[2]), "r"(a[3]), "r"(b[0]), "r"(b[1]));
}
__device__ __forceinline__ void ldm_x4(uint32_t* r, uint32_t addr) {
    asm volatile("ldmatrix.sync.aligned.m8n8.x4.shared.b16 {%0,%1,%2,%3}, [%4];"
                 : "=r"(r[0]), "=r"(r[1]), "=r"(r[2]), "=r"(r[3]) : "r"(addr));
}
__device__ __forceinline__ void ldm_x4_t(uint32_t* r, uint32_t addr) {
    asm volatile("ldmatrix.sync.aligned.m8n8.x4.trans.shared.b16 {%0,%1,%2,%3}, [%4];"
                 : "=r"(r[0]), "=r"(r[1]), "=r"(r[2]), "=r"(r[3]) : "r"(addr));
}
__device__ __forceinline__ uint32_t h2exp2(uint32_t x) {
    uint32_t r; asm("ex2.approx.f16x2 %0, %1;" : "=r"(r) : "r"(x)); return r;
}

// ---------------------------------------------------------------------------
// Small kernels
// ---------------------------------------------------------------------------
__global__ void f2h_kernel(const float* __restrict__ in, __half* __restrict__ out, int n) {
    int i = blockIdx.x * blockDim.x + threadIdx.x;
    if (i < n) out[i] = __float2half(in[i]);
}
__global__ void transpose_kernel(const float* __restrict__ in, __half* __restrict__ out,
                                 int K, int N) {
    __shared__ float t[32][33];
    int k0 = blockIdx.y * 32, n0 = blockIdx.x * 32;
    int tx = threadIdx.x & 31, ty = threadIdx.x >> 5;
#pragma unroll
    for (int i = 0; i < 32; i += 8)
        t[ty + i][tx] = in[(size_t)(k0 + ty + i) * N + n0 + tx];
    __syncthreads();
#pragma unroll
    for (int i = 0; i < 32; i += 8)
        out[(size_t)(n0 + ty + i) * K + k0 + tx] = __float2half(t[tx][ty + i]);
}

// ---------------------------------------------------------------------------
// LayerNorm: fp32 in -> fp16 out
// ---------------------------------------------------------------------------
__global__ void ln_kernel(const float* __restrict__ in,
                          const float* __restrict__ gamma,
                          const float* __restrict__ beta,
                          __half* __restrict__ out) {
    int row = blockIdx.x;
    int tid = threadIdx.x;
    float4 v = ((const float4*)(in + (size_t)row * H))[tid];

    float s = v.x + v.y + v.z + v.w;
    float s2 = v.x * v.x + v.y * v.y + v.z * v.z + v.w * v.w;
    __shared__ float sh_s[8], sh_s2[8];
    float ws = warpSum(s), ws2 = warpSum(s2);
    int wid = tid >> 5, lane = tid & 31;
    if (lane == 0) { sh_s[wid] = ws; sh_s2[wid] = ws2; }
    __syncthreads();
    float tot = 0.f, tot2 = 0.f;
#pragma unroll
    for (int w = 0; w < 8; w++) { tot += sh_s[w]; tot2 += sh_s2[w]; }
    float mean = tot * (1.0f / H);
    float var = tot2 * (1.0f / H) - mean * mean;
    float inv = rsqrtf(var + 1e-5f);

    float4 gm = ((const float4*)gamma)[tid];
    float4 bt = ((const float4*)beta)[tid];
    float o0 = (v.x - mean) * inv * gm.x + bt.x;
    float o1 = (v.y - mean) * inv * gm.y + bt.y;
    float o2 = (v.z - mean) * inv * gm.z + bt.z;
    float o3 = (v.w - mean) * inv * gm.w + bt.w;
    half2 h0 = __floats2half2_rn(o0, o1);
    half2 h1 = __floats2half2_rn(o2, o3);
    ((uint2*)(out + (size_t)row * H))[tid] = make_uint2(
        *(uint32_t*)&h0, *(uint32_t*)&h1);
}

// ---------------------------------------------------------------------------
// FP16 tensor-core GEMM with ldmatrix fragment feed.
//   C[M,N] = A[M,K] @ Wt[N,K]^T (+bias)(+GELU)(+resid)
//   Tile 128x128x32, 256 threads (8 warps, warp tile 32x64), 2-stage cp.async.
// ---------------------------------------------------------------------------
#define KSTR 40

__global__ __launch_bounds__(256, 2)
void gemm_h_kernel(const __half* __restrict__ A, const __half* __restrict__ Wt,
                   const float* __restrict__ bias, const float* __restrict__ resid,
                   float* __restrict__ Cf, __half* __restrict__ Ch,
                   int M, int N, int K, int do_gelu) {
    __shared__ __half sA[2][128 * KSTR];
    __shared__ __half sB[2][128 * KSTR];

    int tid = threadIdx.x;
    int lane = tid & 31, w = tid >> 5;
    int g = lane >> 2, t = lane & 3;
    int wm = w & 3, wn = w >> 2;
    int row0 = blockIdx.y * 128;
    int col0 = blockIdx.x * 128;

    uint32_t sAb[2] = { smem_u32(sA[0]), smem_u32(sA[1]) };
    uint32_t sBb[2] = { smem_u32(sB[0]), smem_u32(sB[1]) };

    int ldrow[2], ldc16[2];
#pragma unroll
    for (int i = 0; i < 2; i++) {
        int idx = i * 256 + tid;
        ldrow[i] = idx >> 2;
        ldc16[i] = idx & 3;
    }

    const int NK = K >> 5;

#pragma unroll
    for (int i = 0; i < 2; i++) {
        int r = ldrow[i], c16 = ldc16[i];
        int gr = row0 + r;
        const __half* ga = A + (size_t)(gr < M ? gr : row0) * K + c16 * 8;
        cp16(sAb[0] + (r * KSTR + c16 * 8) * 2, ga, gr < M ? 16 : 0);
        const __half* gb = Wt + (size_t)(col0 + r) * K + c16 * 8;
        cp16(sBb[0] + (r * KSTR + c16 * 8) * 2, gb, 16);
    }
    CP_COMMIT();

    float c[2][8][4];
#pragma unroll
    for (int mt = 0; mt < 2; mt++)
#pragma unroll
        for (int nt = 0; nt < 8; nt++)
#pragma unroll
            for (int i = 0; i < 4; i++) c[mt][nt][i] = 0.f;

    // ldmatrix lane-address components (same patterns as verified flash kernel)
    int arow_l = (lane & 7) + ((lane & 8) ? 8 : 0);   // A: row within 16
    int acol_l = (lane & 16) ? 8 : 0;                 // A: col half
    int brow_l = (lane & 7) + ((lane & 16) ? 8 : 0);  // B: row within 16
    int bcol_l = (lane & 8) ? 8 : 0;                  // B: col half

    for (int kt = 0; kt < NK; kt++) {
        int s = kt & 1;
        if (kt + 1 < NK) {
            int sn = (kt + 1) & 1;
            int k0 = (kt + 1) << 5;
#pragma unroll
            for (int i = 0; i < 2; i++) {
                int r = ldrow[i], c16 = ldc16[i];
                int gr = row0 + r;
                const __half* ga = A + (size_t)(gr < M ? gr : row0) * K + k0 + c16 * 8;
                cp16(sAb[sn] + (r * KSTR + c16 * 8) * 2, ga, gr < M ? 16 : 0);
                const __half* gb = Wt + (size_t)(col0 + r) * K + k0 + c16 * 8;
                cp16(sBb[sn] + (r * KSTR + c16 * 8) * 2, gb, 16);
            }
        }
        CP_COMMIT();
        CP_WAIT1();
        __syncthreads();

        uint32_t as = sAb[s], bs = sBb[s];
#pragma unroll
        for (int ks = 0; ks < 2; ks++) {
            int kb = ks * 16;
            uint32_t a[2][4];
#pragma unroll
            for (int mt = 0; mt < 2; mt++) {
                int row = wm * 32 + mt * 16 + arow_l;
                ldm_x4(a[mt], as + (row * KSTR + kb + acol_l) * 2);
            }
#pragma unroll
            for (int nt2 = 0; nt2 < 4; nt2++) {
                int row = wn * 64 + nt2 * 16 + brow_l;
                uint32_t bb[4];
                ldm_x4(bb, bs + (row * KSTR + kb + bcol_l) * 2);
#pragma unroll
                for (int mt = 0; mt < 2; mt++) {
                    mma_f16(c[mt][nt2 * 2], a[mt], bb);
                    mma_f16(c[mt][nt2 * 2 + 1], a[mt], bb + 2);
                }
            }
        }
        __syncthreads();
    }

#pragma unroll
    for (int mt = 0; mt < 2; mt++) {
        int r = row0 + wm * 32 + mt * 16 + g;
#pragma unroll
        for (int nt = 0; nt < 8; nt++) {
            int cc = col0 + wn * 64 + nt * 8 + 2 * t;
            float v0 = c[mt][nt][0], v1 = c[mt][nt][1];
            float v2 = c[mt][nt][2], v3 = c[mt][nt][3];
            if (bias) {
                float b0 = bias[cc], b1 = bias[cc + 1];
                v0 += b0; v1 += b1; v2 += b0; v3 += b1;
            }
            if (do_gelu) {
                v0 = 0.5f * v0 * (1.0f + erff(v0 * 0.70710678118654752f));
                v1 = 0.5f * v1 * (1.0f + erff(v1 * 0.70710678118654752f));
                v2 = 0.5f * v2 * (1.0f + erff(v2 * 0.70710678118654752f));
                v3 = 0.5f * v3 * (1.0f + erff(v3 * 0.70710678118654752f));
            }
            if (r < M) {
                float o0 = v0, o1 = v1;
                if (resid) { o0 += resid[(size_t)r * N + cc]; o1 += resid[(size_t)r * N + cc + 1]; }
                if (Cf) { Cf[(size_t)r * N + cc] = o0; Cf[(size_t)r * N + cc + 1] = o1; }
                if (Ch) *(half2*)(Ch + (size_t)r * N + cc) = __floats2half2_rn(o0, o1);
            }
            if (r + 8 < M) {
                float o2 = v2, o3 = v3;
                if (resid) { o2 += resid[(size_t)(r + 8) * N + cc]; o3 += resid[(size_t)(r + 8) * N + cc + 1]; }
                if (Cf) { Cf[(size_t)(r + 8) * N + cc] = o2; Cf[(size_t)(r + 8) * N + cc + 1] = o3; }
                if (Ch) *(half2*)(Ch + (size_t)(r + 8) * N + cc) = __floats2half2_rn(o2, o3);
            }
        }
    }
}

// ---------------------------------------------------------------------------
// FP16 flash attention (strided Q and K/V for fused-QKV buffers).
// ---------------------------------------------------------------------------
#define FA_BM 64
#define FA_BN 64
#define FSTR 72
#define SCALE_L2E 0.18033688f   // 0.125 * log2(e)

__global__ __launch_bounds__(128)
void fattn_kernel(const __half* __restrict__ Qg, int QS,
                  const __half* __restrict__ Kg, const __half* __restrict__ Vg, int KS,
                  __half* __restrict__ Og, int Slen) {
    __shared__ __half sQ[FA_BM * FSTR];
    __shared__ __half sK[FA_BN * FSTR];
    __shared__ __half sV[FA_BN * FSTR];

    int b = blockIdx.z, h = blockIdx.y;
    int q0 = blockIdx.x * FA_BM;
    int tid = threadIdx.x, w = tid >> 5, lane = tid & 31;
    int g = lane >> 2, t = lane & 3;

    uint32_t sQb = smem_u32(sQ), sKb = smem_u32(sK), sVb = smem_u32(sV);

#pragma unroll
    for (int i = 0; i < 4; i++) {
        int idx = i * 128 + tid;
        int r = idx >> 3, c = (idx & 7) * 8;
        const __half* gp = Qg + (size_t)(b * T + q0 + r) * QS + h * HD + c;
        cp16(sQb + (r * FSTR + c) * 2, gp, 16);
    }
    CP_COMMIT();
    CP_WAIT0();
    __syncthreads();

    uint32_t aq[4][4];
    {
        int row = w * 16 + (lane & 7) + ((lane & 8) ? 8 : 0);
#pragma unroll
        for (int kt = 0; kt < 4; kt++) {
            int col = kt * 16 + ((lane & 16) ? 8 : 0);
            ldm_x4(aq[kt], sQb + (row * FSTR + col) * 2);
        }
    }

    float m0 = -1e30f, m1 = -1e30f, l0 = 0.f, l1 = 0.f;
    float o[8][4];
#pragma unroll
    for (int dt = 0; dt < 8; dt++)
#pragma unroll
        for (int i = 0; i < 4; i++) o[dt][i] = 0.f;

    for (int j0 = 0; j0 < Slen; j0 += FA_BN) {
        __syncthreads();
#pragma unroll
        for (int i = 0; i < 4; i++) {
            int idx = i * 128 + tid;
            int r = idx >> 3, c = (idx & 7) * 8;
            int j = j0 + r;
            int ok = (j < Slen) ? 16 : 0;
            size_t goff = (size_t)(b * Slen + (j < Slen ? j : 0)) * KS + h * HD + c;
            cp16(sKb + (r * FSTR + c) * 2, Kg + goff, ok);
            cp16(sVb + (r * FSTR + c) * 2, Vg + goff, ok);
        }
        CP_COMMIT();
        CP_WAIT0();
        __syncthreads();

        float c[8][4];
#pragma unroll
        for (int nt = 0; nt < 8; nt++)
#pragma unroll
            for (int i = 0; i < 4; i++) c[nt][i] = 0.f;

        {
            int krow = (lane & 7) + ((lane & 16) ? 8 : 0);
            int kcol = (lane & 8) ? 8 : 0;
#pragma unroll
            for (int kt = 0; kt < 4; kt++) {
#pragma unroll
                for (int nt2 = 0; nt2 < 4; nt2++) {
                    uint32_t bb[4];
                    ldm_x4(bb, sKb + ((nt2 * 16 + krow) * FSTR + kt * 16 + kcol) * 2);
                    mma_f16(c[nt2 * 2], aq[kt], bb);
                    mma_f16(c[nt2 * 2 + 1], aq[kt], bb + 2);
                }
            }
        }

#pragma unroll
        for (int nt = 0; nt < 8; nt++)
#pragma unroll
            for (int i = 0; i < 4; i++) c[nt][i] *= SCALE_L2E;
        if (j0 + FA_BN > Slen) {
#pragma unroll
            for (int nt = 0; nt < 8; nt++) {
                int ja = j0 + nt * 8 + 2 * t;
                if (ja >= Slen) { c[nt][0] = -1e30f; c[nt][2] = -1e30f; }
                if (ja + 1 >= Slen) { c[nt][1] = -1e30f; c[nt][3] = -1e30f; }
            }
        }

        float tm0 = -1e30f, tm1 = -1e30f;
#pragma unroll
        for (int nt = 0; nt < 8; nt++) {
            tm0 = fmaxf(tm0, fmaxf(c[nt][0], c[nt][1]));
            tm1 = fmaxf(tm1, fmaxf(c[nt][2], c[nt][3]));
        }
        tm0 = fmaxf(tm0, __shfl_xor_sync(0xffffffffu, tm0, 1));
        tm0 = fmaxf(tm0, __shfl_xor_sync(0xffffffffu, tm0, 2));
        tm1 = fmaxf(tm1, __shfl_xor_sync(0xffffffffu, tm1, 1));
        tm1 = fmaxf(tm1, __shfl_xor_sync(0xffffffffu, tm1, 2));

        float mn0 = fmaxf(m0, tm0), mn1 = fmaxf(m1, tm1);
        float al0 = exp2f(m0 - mn0), al1 = exp2f(m1 - mn1);
        m0 = mn0; m1 = mn1;

        uint32_t ph[8][2];
        float s0 = 0.f, s1 = 0.f;
#pragma unroll
        for (int nt = 0; nt < 8; nt++) {
            half2 x0 = __floats2half2_rn(c[nt][0] - mn0, c[nt][1] - mn0);
            half2 x1 = __floats2half2_rn(c[nt][2] - mn1, c[nt][3] - mn1);
            ph[nt][0] = h2exp2(*(uint32_t*)&x0);
            ph[nt][1] = h2exp2(*(uint32_t*)&x1);
            float2 f0 = __half22float2(*(half2*)&ph[nt][0]);
            float2 f1 = __half22float2(*(half2*)&ph[nt][1]);
            s0 += f0.x + f0.y;
            s1 += f1.x + f1.y;
        }
        s0 += __shfl_xor_sync(0xffffffffu, s0, 1);
        s0 += __shfl_xor_sync(0xffffffffu, s0, 2);
        s1 += __shfl_xor_sync(0xffffffffu, s1, 1);
        s1 += __shfl_xor_sync(0xffffffffu, s1, 2);
        l0 = l0 * al0 + s0;
        l1 = l1 * al1 + s1;

#pragma unroll
        for (int dt = 0; dt < 8; dt++) {
            o[dt][0] *= al0; o[dt][1] *= al0;
            o[dt][2] *= al1; o[dt][3] *= al1;
        }

        {
            int vrow = (lane & 7) + ((lane & 8) ? 8 : 0);
            int vcol = (lane & 16) ? 8 : 0;
#pragma unroll
            for (int kt = 0; kt < 4; kt++) {
                uint32_t af[4] = { ph[2 * kt][0], ph[2 * kt][1],
                                   ph[2 * kt + 1][0], ph[2 * kt + 1][1] };
#pragma unroll
                for (int dt2 = 0; dt2 < 4; dt2++) {
                    uint32_t bb[4];
                    ldm_x4_t(bb, sVb + ((kt * 16 + vrow) * FSTR + dt2 * 16 + vcol) * 2);
                    mma_f16(o[dt2 * 2], af, bb);
                    mma_f16(o[dt2 * 2 + 1], af, bb + 2);
                }
            }
        }
    }

    float inv0 = 1.0f / l0, inv1 = 1.0f / l1;
    int row0 = q0 + w * 16 + g;
#pragma unroll
    for (int dt = 0; dt < 8; dt++) {
        int col = dt * 8 + 2 * t;
        half2 h0 = __floats2half2_rn(o[dt][0] * inv0, o[dt][1] * inv0);
        half2 h1 = __floats2half2_rn(o[dt][2] * inv1, o[dt][3] * inv1);
        *(half2*)(Og + ((size_t)(b * T + row0) * H) + h * HD + col) = h0;
        *(half2*)(Og + ((size_t)(b * T + row0 + 8) * H) + h * HD + col) = h1;
    }
}

// ---------------------------------------------------------------------------
// Orchestration
// ---------------------------------------------------------------------------
static inline void gemm(const __half* A, const __half* Wt, const float* bias,
                        const float* resid, float* Cf, __half* Ch,
                        int M, int N, int K, int gelu) {
    dim3 grid(N / 128, (M + 127) / 128);
    gemm_h_kernel<<<grid, 256>>>(A, Wt, bias, resid, Cf, Ch, M, N, K, gelu);
}
static inline void wtrans(const float* in, __half* out, int K, int N) {
    transpose_kernel<<<dim3(N / 32, K / 32), 256>>>(in, out, K, N);
}

extern "C" void kernel_launch(void* const* d_in, const int* in_sizes, int n_in,
                              void* d_out, int out_size) {
    const float* x    = (const float*)d_in[0];
    const float* ctx  = (const float*)d_in[1];
    const float* sq_w = (const float*)d_in[2];
    const float* sk_w = (const float*)d_in[3];
    const float* sv_w = (const float*)d_in[4];
    const float* so_w = (const float*)d_in[5];
    const float* so_b = (const float*)d_in[6];
    const float* cq_w = (const float*)d_in[7];
    const float* ck_w = (const float*)d_in[8];
    const float* cv_w = (const float*)d_in[9];
    const float* co_w = (const float*)d_in[10];
    const float* co_b = (const float*)d_in[11];
    const float* n1_g = (const float*)d_in[12];
    const float* n1_b = (const float*)d_in[13];
    const float* n2_g = (const float*)d_in[14];
    const float* n2_b = (const float*)d_in[15];
    const float* n3_g = (const float*)d_in[16];
    const float* n3_b = (const float*)d_in[17];
    const float* n4_g = (const float*)d_in[18];
    const float* n4_b = (const float*)d_in[19];
    const float* f1_w1 = (const float*)d_in[20];
    const float* f1_b1 = (const float*)d_in[21];
    const float* f1_w2 = (const float*)d_in[22];
    const float* f1_b2 = (const float*)d_in[23];
    const float* f2_w1 = (const float*)d_in[24];
    const float* f2_b1 = (const float*)d_in[25];
    const float* f2_w2 = (const float*)d_in[26];
    const float* f2_b2 = (const float*)d_in[27];
    float* out = (float*)d_out;

    float* px;
    __half *plnh, *pqkv, *pqh, *pckv, *pah, *phh, *pctxh, *pwt;
    cudaGetSymbolAddress((void**)&px, g_x);
    cudaGetSymbolAddress((void**)&plnh, g_ln_h);
    cudaGetSymbolAddress((void**)&pqkv, g_qkv_h);
    cudaGetSymbolAddress((void**)&pqh, g_q_h);
    cudaGetSymbolAddress((void**)&pckv, g_ckv_h);
    cudaGetSymbolAddress((void**)&pah, g_attn_h);
    cudaGetSymbolAddress((void**)&phh, g_hid_h);
    cudaGetSymbolAddress((void**)&pctxh, g_ctx_h);
    cudaGetSymbolAddress((void**)&pwt, g_wt);

    const int NCTX = BATCH * SC * CD;

    f2h_kernel<<<(NCTX + 255) / 256, 256>>>(ctx, pctxh, NCTX);
    wtrans(sq_w, pwt + WT_Q, H, H);
    wtrans(sk_w, pwt + WT_K, H, H);
    wtrans(sv_w, pwt + WT_V, H, H);
    wtrans(so_w, pwt + WT_O, H, H);
    wtrans(cq_w, pwt + WT_CQ, H, H);
    wtrans(co_w, pwt + WT_CO, H, H);
    wtrans(ck_w, pwt + WT_CK, CD, H);
    wtrans(cv_w, pwt + WT_CV, CD, H);
    wtrans(f1_w1, pwt + WT_F1A, H, FF);
    wtrans(f1_w2, pwt + WT_F1B, FF, H);
    wtrans(f2_w1, pwt + WT_F2A, H, FF);
    wtrans(f2_w2, pwt + WT_F2B, FF, H);

    // ---------------- Stage A: self-attention ----------------
    ln_kernel<<<BT, 256>>>(x, n1_g, n1_b, plnh);     // LN1 reads original x
    gemm(plnh, pwt + WT_Q, nullptr, nullptr, nullptr, pqkv, BT, 3 * H, H, 0); // fused QKV
    fattn_kernel<<<dim3(T / FA_BM, NH, BATCH), 128>>>(
        pqkv, 3 * H, pqkv + H, pqkv + 2 * H, 3 * H, pah, T);
    gemm(pah, pwt + WT_O, so_b, x, px, nullptr, BT, H, H, 0);  // resid = original x

    // ---------------- Stage B: FFN 1 ----------------
    ln_kernel<<<BT, 256>>>(px, n2_g, n2_b, plnh);
    gemm(plnh, pwt + WT_F1A, f1_b1, nullptr, nullptr, phh, BT, FF, H, 1);
    gemm(phh, pwt + WT_F1B, f1_b2, px, px, nullptr, BT, H, FF, 0);

    // ---------------- Stage C: cross-attention ----------------
    ln_kernel<<<BT, 256>>>(px, n3_g, n3_b, plnh);
    gemm(plnh, pwt + WT_CQ, nullptr, nullptr, nullptr, pqh, BT, H, H, 0);
    gemm(pctxh, pwt + WT_CK, nullptr, nullptr, nullptr, pckv, BATCH * SC, 2 * H, CD, 0); // fused cross K/V
    fattn_kernel<<<dim3(T / FA_BM, NH, BATCH), 128>>>(
        pqh, H, pckv, pckv + H, 2 * H, pah, SC);
    gemm(pah, pwt + WT_CO, co_b, px, px, nullptr, BT, H, H, 0);

    // ---------------- Stage D: FFN 2 ----------------
    ln_kernel<<<BT, 256>>>(px, n4_g, n4_b, plnh);
    gemm(plnh, pwt + WT_F2A, f2_b1, nullptr, nullptr, phh, BT, FF, H, 1);
    gemm(phh, pwt + WT_F2B, f2_b2, px, out, nullptr, BT, H, FF, 0);
}

// round 9
// speedup vs baseline: 1.3963x; 1.3963x over previous
#include <cuda_runtime.h>
#include <cuda_fp16.h>
#include <math.h>
#include <stddef.h>
#include <stdint.h>

// ---------------------------------------------------------------------------
// Problem dims
// ---------------------------------------------------------------------------
#define BATCH 4
#define T 1024
#define H 1024
#define NH 16
#define HD 64
#define CD 768
#define SC 77
#define FF 4096
#define BT (BATCH * T)

// ---------------------------------------------------------------------------
// Scratch
// ---------------------------------------------------------------------------
__device__ float g_x[BT * H];           // residual stream (fp32)
__device__ __half g_ln_h[BT * H];       // LN output (fp16)
__device__ __half g_qkv_h[BT * 3 * H];  // fused QKV (self)
__device__ __half g_q_h[BT * H];        // cross-attn Q
__device__ __half g_ckv_h[BATCH * SC * 2 * H]; // fused cross K/V
__device__ __half g_attn_h[BT * H];
__device__ __half g_hid_h[BT * FF];
__device__ __half g_ctx_h[BATCH * SC * CD];
// transposed fp16 weights, [N,K] row-major. Q,K,V contiguous; CK,CV contiguous.
#define WT_Q   0
#define WT_K   (WT_Q + H * H)
#define WT_V   (WT_K + H * H)
#define WT_O   (WT_V + H * H)
#define WT_CQ  (WT_O + H * H)
#define WT_CO  (WT_CQ + H * H)
#define WT_CK  (WT_CO + H * H)
#define WT_CV  (WT_CK + H * CD)
#define WT_F1A (WT_CV + H * CD)
#define WT_F1B (WT_F1A + FF * H)
#define WT_F2A (WT_F1B + H * FF)
#define WT_F2B (WT_F2A + FF * H)
#define WT_TOTAL (WT_F2B + H * FF)
__device__ __half g_wt[WT_TOTAL];

// ---------------------------------------------------------------------------
// Utility
// ---------------------------------------------------------------------------
__device__ __forceinline__ float warpSum(float v) {
#pragma unroll
    for (int o = 16; o; o >>= 1) v += __shfl_xor_sync(0xffffffffu, v, o);
    return v;
}
__device__ __forceinline__ uint32_t smem_u32(const void* p) {
    uint32_t a;
    asm("{ .reg .u64 t; cvta.to.shared.u64 t, %1; cvt.u32.u64 %0, t; }" : "=r"(a) : "l"(p));
    return a;
}
__device__ __forceinline__ void cp16(uint32_t saddr, const void* g, int srcBytes) {
    asm volatile("cp.async.cg.shared.global [%0], [%1], 16, %2;"
                 :: "r"(saddr), "l"(g), "r"(srcBytes) : "memory");
}
#define CP_COMMIT() asm volatile("cp.async.commit_group;" ::: "memory")
#define CP_WAIT1()  asm volatile("cp.async.wait_group 1;" ::: "memory")
#define CP_WAIT0()  asm volatile("cp.async.wait_group 0;" ::: "memory")

__device__ __forceinline__ void mma_f16(float* c, const uint32_t* a, const uint32_t* b) {
    asm volatile(
        "mma.sync.aligned.m16n8k16.row.col.f32.f16.f16.f32 "
        "{%0,%1,%2,%3}, {%4,%5,%6,%7}, {%8,%9}, {%0,%1,%2,%3};"
        : "+f"(c[0]), "+f"(c[1]), "+f"(c[2]), "+f"(c[3])
        : "r"(a[0]), "r"(a[1]), "r"(a[2]), "r"(a[3]), "r"(b[0]), "r"(b[1]));
}
__device__ __forceinline__ void ldm_x4(uint32_t* r, uint32_t addr) {
    asm volatile("ldmatrix.sync.aligned.m8n8.x4.shared.b16 {%0,%1,%2,%3}, [%4];"
                 : "=r"(r[0]), "=r"(r[1]), "=r"(r[2]), "=r"(r[3]) : "r"(addr));
}
__device__ __forceinline__ void ldm_x4_t(uint32_t* r, uint32_t addr) {
    asm volatile("ldmatrix.sync.aligned.m8n8.x4.trans.shared.b16 {%0,%1,%2,%3}, [%4];"
                 : "=r"(r[0]), "=r"(r[1]), "=r"(r[2]), "=r"(r[3]) : "r"(addr));
}
__device__ __forceinline__ uint32_t h2exp2(uint32_t x) {
    uint32_t r; asm("ex2.approx.f16x2 %0, %1;" : "=r"(r) : "r"(x)); return r;
}

// ---------------------------------------------------------------------------
// Small kernels
// ---------------------------------------------------------------------------
__global__ void f2h_kernel(const float* __restrict__ in, __half* __restrict__ out, int n) {
    int i = blockIdx.x * blockDim.x + threadIdx.x;
    if (i < n) out[i] = __float2half(in[i]);
}
__global__ void transpose_kernel(const float* __restrict__ in, __half* __restrict__ out,
                                 int K, int N) {
    __shared__ float t[32][33];
    int k0 = blockIdx.y * 32, n0 = blockIdx.x * 32;
    int tx = threadIdx.x & 31, ty = threadIdx.x >> 5;
#pragma unroll
    for (int i = 0; i < 32; i += 8)
        t[ty + i][tx] = in[(size_t)(k0 + ty + i) * N + n0 + tx];
    __syncthreads();
#pragma unroll
    for (int i = 0; i < 32; i += 8)
        out[(size_t)(n0 + ty + i) * K + k0 + tx] = __float2half(t[tx][ty + i]);
}

// ---------------------------------------------------------------------------
// LayerNorm: fp32 in -> fp16 out
// ---------------------------------------------------------------------------
__global__ void ln_kernel(const float* __restrict__ in,
                          const float* __restrict__ gamma,
                          const float* __restrict__ beta,
                          __half* __restrict__ out) {
    int row = blockIdx.x;
    int tid = threadIdx.x;
    float4 v = ((const float4*)(in + (size_t)row * H))[tid];

    float s = v.x + v.y + v.z + v.w;
    float s2 = v.x * v.x + v.y * v.y + v.z * v.z + v.w * v.w;
    __shared__ float sh_s[8], sh_s2[8];
    float ws = warpSum(s), ws2 = warpSum(s2);
    int wid = tid >> 5, lane = tid & 31;
    if (lane == 0) { sh_s[wid] = ws; sh_s2[wid] = ws2; }
    __syncthreads();
    float tot = 0.f, tot2 = 0.f;
#pragma unroll
    for (int w = 0; w < 8; w++) { tot += sh_s[w]; tot2 += sh_s2[w]; }
    float mean = tot * (1.0f / H);
    float var = tot2 * (1.0f / H) - mean * mean;
    float inv = rsqrtf(var + 1e-5f);

    float4 gm = ((const float4*)gamma)[tid];
    float4 bt = ((const float4*)beta)[tid];
    float o0 = (v.x - mean) * inv * gm.x + bt.x;
    float o1 = (v.y - mean) * inv * gm.y + bt.y;
    float o2 = (v.z - mean) * inv * gm.z + bt.z;
    float o3 = (v.w - mean) * inv * gm.w + bt.w;
    half2 h0 = __floats2half2_rn(o0, o1);
    half2 h1 = __floats2half2_rn(o2, o3);
    ((uint2*)(out + (size_t)row * H))[tid] = make_uint2(
        *(uint32_t*)&h0, *(uint32_t*)&h1);
}

// ---------------------------------------------------------------------------
// FP16 tensor-core GEMM (R7 mainloop: scalar fragment feed).
//   C[M,N] = A[M,K] @ Wt[N,K]^T (+bias)(+GELU)(+resid)
// ---------------------------------------------------------------------------
#define KSTR 40

__global__ __launch_bounds__(256, 2)
void gemm_h_kernel(const __half* __restrict__ A, const __half* __restrict__ Wt,
                   const float* __restrict__ bias, const float* __restrict__ resid,
                   float* __restrict__ Cf, __half* __restrict__ Ch,
                   int M, int N, int K, int do_gelu) {
    __shared__ __half sA[2][128 * KSTR];
    __shared__ __half sB[2][128 * KSTR];

    int tid = threadIdx.x;
    int lane = tid & 31, w = tid >> 5;
    int g = lane >> 2, t = lane & 3;
    int wm = w & 3, wn = w >> 2;
    int row0 = blockIdx.y * 128;
    int col0 = blockIdx.x * 128;

    uint32_t sAb[2] = { smem_u32(sA[0]), smem_u32(sA[1]) };
    uint32_t sBb[2] = { smem_u32(sB[0]), smem_u32(sB[1]) };

    int ldrow[2], ldc16[2];
#pragma unroll
    for (int i = 0; i < 2; i++) {
        int idx = i * 256 + tid;
        ldrow[i] = idx >> 2;
        ldc16[i] = idx & 3;
    }

    const int NK = K >> 5;

#pragma unroll
    for (int i = 0; i < 2; i++) {
        int r = ldrow[i], c16 = ldc16[i];
        int gr = row0 + r;
        const __half* ga = A + (size_t)(gr < M ? gr : row0) * K + c16 * 8;
        cp16(sAb[0] + (r * KSTR + c16 * 8) * 2, ga, gr < M ? 16 : 0);
        const __half* gb = Wt + (size_t)(col0 + r) * K + c16 * 8;
        cp16(sBb[0] + (r * KSTR + c16 * 8) * 2, gb, 16);
    }
    CP_COMMIT();

    float c[2][8][4];
#pragma unroll
    for (int mt = 0; mt < 2; mt++)
#pragma unroll
        for (int nt = 0; nt < 8; nt++)
#pragma unroll
            for (int i = 0; i < 4; i++) c[mt][nt][i] = 0.f;

    for (int kt = 0; kt < NK; kt++) {
        int s = kt & 1;
        if (kt + 1 < NK) {
            int sn = (kt + 1) & 1;
            int k0 = (kt + 1) << 5;
#pragma unroll
            for (int i = 0; i < 2; i++) {
                int r = ldrow[i], c16 = ldc16[i];
                int gr = row0 + r;
                const __half* ga = A + (size_t)(gr < M ? gr : row0) * K + k0 + c16 * 8;
                cp16(sAb[sn] + (r * KSTR + c16 * 8) * 2, ga, gr < M ? 16 : 0);
                const __half* gb = Wt + (size_t)(col0 + r) * K + k0 + c16 * 8;
                cp16(sBb[sn] + (r * KSTR + c16 * 8) * 2, gb, 16);
            }
        }
        CP_COMMIT();
        CP_WAIT1();
        __syncthreads();

        const __half* as = sA[s];
        const __half* bs = sB[s];
#pragma unroll
        for (int ks = 0; ks < 2; ks++) {
            int kb = ks * 16;
            uint32_t a[2][4], b[8][2];
#pragma unroll
            for (int mt = 0; mt < 2; mt++) {
                int m = wm * 32 + mt * 16 + g;
                a[mt][0] = *(const uint32_t*)(as + m * KSTR + kb + 2 * t);
                a[mt][1] = *(const uint32_t*)(as + (m + 8) * KSTR + kb + 2 * t);
                a[mt][2] = *(const uint32_t*)(as + m * KSTR + kb + 2 * t + 8);
                a[mt][3] = *(const uint32_t*)(as + (m + 8) * KSTR + kb + 2 * t + 8);
            }
#pragma unroll
            for (int nt = 0; nt < 8; nt++) {
                int n = wn * 64 + nt * 8 + g;
                b[nt][0] = *(const uint32_t*)(bs + n * KSTR + kb + 2 * t);
                b[nt][1] = *(const uint32_t*)(bs + n * KSTR + kb + 2 * t + 8);
            }
#pragma unroll
            for (int mt = 0; mt < 2; mt++)
#pragma unroll
                for (int nt = 0; nt < 8; nt++)
                    mma_f16(c[mt][nt], a[mt], b[nt]);
        }
        __syncthreads();
    }

#pragma unroll
    for (int mt = 0; mt < 2; mt++) {
        int r = row0 + wm * 32 + mt * 16 + g;
#pragma unroll
        for (int nt = 0; nt < 8; nt++) {
            int cc = col0 + wn * 64 + nt * 8 + 2 * t;
            float v0 = c[mt][nt][0], v1 = c[mt][nt][1];
            float v2 = c[mt][nt][2], v3 = c[mt][nt][3];
            if (bias) {
                float b0 = bias[cc], b1 = bias[cc + 1];
                v0 += b0; v1 += b1; v2 += b0; v3 += b1;
            }
            if (do_gelu) {
                v0 = 0.5f * v0 * (1.0f + erff(v0 * 0.70710678118654752f));
                v1 = 0.5f * v1 * (1.0f + erff(v1 * 0.70710678118654752f));
                v2 = 0.5f * v2 * (1.0f + erff(v2 * 0.70710678118654752f));
                v3 = 0.5f * v3 * (1.0f + erff(v3 * 0.70710678118654752f));
            }
            if (r < M) {
                float o0 = v0, o1 = v1;
                if (resid) { o0 += resid[(size_t)r * N + cc]; o1 += resid[(size_t)r * N + cc + 1]; }
                if (Cf) { Cf[(size_t)r * N + cc] = o0; Cf[(size_t)r * N + cc + 1] = o1; }
                if (Ch) *(half2*)(Ch + (size_t)r * N + cc) = __floats2half2_rn(o0, o1);
            }
            if (r + 8 < M) {
                float o2 = v2, o3 = v3;
                if (resid) { o2 += resid[(size_t)(r + 8) * N + cc]; o3 += resid[(size_t)(r + 8) * N + cc + 1]; }
                if (Cf) { Cf[(size_t)(r + 8) * N + cc] = o2; Cf[(size_t)(r + 8) * N + cc + 1] = o3; }
                if (Ch) *(half2*)(Ch + (size_t)(r + 8) * N + cc) = __floats2half2_rn(o2, o3);
            }
        }
    }
}

// ---------------------------------------------------------------------------
// FP16 flash attention (strided Q and K/V for fused-QKV buffers).
// ---------------------------------------------------------------------------
#define FA_BM 64
#define FA_BN 64
#define FSTR 72
#define SCALE_L2E 0.18033688f   // 0.125 * log2(e)

__global__ __launch_bounds__(128)
void fattn_kernel(const __half* __restrict__ Qg, int QS,
                  const __half* __restrict__ Kg, const __half* __restrict__ Vg, int KS,
                  __half* __restrict__ Og, int Slen) {
    __shared__ __half sQ[FA_BM * FSTR];
    __shared__ __half sK[FA_BN * FSTR];
    __shared__ __half sV[FA_BN * FSTR];

    int b = blockIdx.z, h = blockIdx.y;
    int q0 = blockIdx.x * FA_BM;
    int tid = threadIdx.x, w = tid >> 5, lane = tid & 31;
    int g = lane >> 2, t = lane & 3;

    uint32_t sQb = smem_u32(sQ), sKb = smem_u32(sK), sVb = smem_u32(sV);

#pragma unroll
    for (int i = 0; i < 4; i++) {
        int idx = i * 128 + tid;
        int r = idx >> 3, c = (idx & 7) * 8;
        const __half* gp = Qg + (size_t)(b * T + q0 + r) * QS + h * HD + c;
        cp16(sQb + (r * FSTR + c) * 2, gp, 16);
    }
    CP_COMMIT();
    CP_WAIT0();
    __syncthreads();

    uint32_t aq[4][4];
    {
        int row = w * 16 + (lane & 7) + ((lane & 8) ? 8 : 0);
#pragma unroll
        for (int kt = 0; kt < 4; kt++) {
            int col = kt * 16 + ((lane & 16) ? 8 : 0);
            ldm_x4(aq[kt], sQb + (row * FSTR + col) * 2);
        }
    }

    float m0 = -1e30f, m1 = -1e30f, l0 = 0.f, l1 = 0.f;
    float o[8][4];
#pragma unroll
    for (int dt = 0; dt < 8; dt++)
#pragma unroll
        for (int i = 0; i < 4; i++) o[dt][i] = 0.f;

    for (int j0 = 0; j0 < Slen; j0 += FA_BN) {
        __syncthreads();
#pragma unroll
        for (int i = 0; i < 4; i++) {
            int idx = i * 128 + tid;
            int r = idx >> 3, c = (idx & 7) * 8;
            int j = j0 + r;
            int ok = (j < Slen) ? 16 : 0;
            size_t goff = (size_t)(b * Slen + (j < Slen ? j : 0)) * KS + h * HD + c;
            cp16(sKb + (r * FSTR + c) * 2, Kg + goff, ok);
            cp16(sVb + (r * FSTR + c) * 2, Vg + goff, ok);
        }
        CP_COMMIT();
        CP_WAIT0();
        __syncthreads();

        float c[8][4];
#pragma unroll
        for (int nt = 0; nt < 8; nt++)
#pragma unroll
            for (int i = 0; i < 4; i++) c[nt][i] = 0.f;

        {
            int krow = (lane & 7) + ((lane & 16) ? 8 : 0);
            int kcol = (lane & 8) ? 8 : 0;
#pragma unroll
            for (int kt = 0; kt < 4; kt++) {
#pragma unroll
                for (int nt2 = 0; nt2 < 4; nt2++) {
                    uint32_t bb[4];
                    ldm_x4(bb, sKb + ((nt2 * 16 + krow) * FSTR + kt * 16 + kcol) * 2);
                    mma_f16(c[nt2 * 2], aq[kt], bb);
                    mma_f16(c[nt2 * 2 + 1], aq[kt], bb + 2);
                }
            }
        }

#pragma unroll
        for (int nt = 0; nt < 8; nt++)
#pragma unroll
            for (int i = 0; i < 4; i++) c[nt][i] *= SCALE_L2E;
        if (j0 + FA_BN > Slen) {
#pragma unroll
            for (int nt = 0; nt < 8; nt++) {
                int ja = j0 + nt * 8 + 2 * t;
                if (ja >= Slen) { c[nt][0] = -1e30f; c[nt][2] = -1e30f; }
                if (ja + 1 >= Slen) { c[nt][1] = -1e30f; c[nt][3] = -1e30f; }
            }
        }

        float tm0 = -1e30f, tm1 = -1e30f;
#pragma unroll
        for (int nt = 0; nt < 8; nt++) {
            tm0 = fmaxf(tm0, fmaxf(c[nt][0], c[nt][1]));
            tm1 = fmaxf(tm1, fmaxf(c[nt][2], c[nt][3]));
        }
        tm0 = fmaxf(tm0, __shfl_xor_sync(0xffffffffu, tm0, 1));
        tm0 = fmaxf(tm0, __shfl_xor_sync(0xffffffffu, tm0, 2));
        tm1 = fmaxf(tm1, __shfl_xor_sync(0xffffffffu, tm1, 1));
        tm1 = fmaxf(tm1, __shfl_xor_sync(0xffffffffu, tm1, 2));

        float mn0 = fmaxf(m0, tm0), mn1 = fmaxf(m1, tm1);
        float al0 = exp2f(m0 - mn0), al1 = exp2f(m1 - mn1);
        m0 = mn0; m1 = mn1;

        uint32_t ph[8][2];
        float s0 = 0.f, s1 = 0.f;
#pragma unroll
        for (int nt = 0; nt < 8; nt++) {
            half2 x0 = __floats2half2_rn(c[nt][0] - mn0, c[nt][1] - mn0);
            half2 x1 = __floats2half2_rn(c[nt][2] - mn1, c[nt][3] - mn1);
            ph[nt][0] = h2exp2(*(uint32_t*)&x0);
            ph[nt][1] = h2exp2(*(uint32_t*)&x1);
            float2 f0 = __half22float2(*(half2*)&ph[nt][0]);
            float2 f1 = __half22float2(*(half2*)&ph[nt][1]);
            s0 += f0.x + f0.y;
            s1 += f1.x + f1.y;
        }
        s0 += __shfl_xor_sync(0xffffffffu, s0, 1);
        s0 += __shfl_xor_sync(0xffffffffu, s0, 2);
        s1 += __shfl_xor_sync(0xffffffffu, s1, 1);
        s1 += __shfl_xor_sync(0xffffffffu, s1, 2);
        l0 = l0 * al0 + s0;
        l1 = l1 * al1 + s1;

#pragma unroll
        for (int dt = 0; dt < 8; dt++) {
            o[dt][0] *= al0; o[dt][1] *= al0;
            o[dt][2] *= al1; o[dt][3] *= al1;
        }

        {
            int vrow = (lane & 7) + ((lane & 8) ? 8 : 0);
            int vcol = (lane & 16) ? 8 : 0;
#pragma unroll
            for (int kt = 0; kt < 4; kt++) {
                uint32_t af[4] = { ph[2 * kt][0], ph[2 * kt][1],
                                   ph[2 * kt + 1][0], ph[2 * kt + 1][1] };
#pragma unroll
                for (int dt2 = 0; dt2 < 4; dt2++) {
                    uint32_t bb[4];
                    ldm_x4_t(bb, sVb + ((kt * 16 + vrow) * FSTR + dt2 * 16 + vcol) * 2);
                    mma_f16(o[dt2 * 2], af, bb);
                    mma_f16(o[dt2 * 2 + 1], af, bb + 2);
                }
            }
        }
    }

    float inv0 = 1.0f / l0, inv1 = 1.0f / l1;
    int row0 = q0 + w * 16 + g;
#pragma unroll
    for (int dt = 0; dt < 8; dt++) {
        int col = dt * 8 + 2 * t;
        half2 h0 = __floats2half2_rn(o[dt][0] * inv0, o[dt][1] * inv0);
        half2 h1 = __floats2half2_rn(o[dt][2] * inv1, o[dt][3] * inv1);
        *(half2*)(Og + ((size_t)(b * T + row0) * H) + h * HD + col) = h0;
        *(half2*)(Og + ((size_t)(b * T + row0 + 8) * H) + h * HD + col) = h1;
    }
}

// ---------------------------------------------------------------------------
// Orchestration
// ---------------------------------------------------------------------------
static inline void gemm(const __half* A, const __half* Wt, const float* bias,
                        const float* resid, float* Cf, __half* Ch,
                        int M, int N, int K, int gelu) {
    dim3 grid(N / 128, (M + 127) / 128);
    gemm_h_kernel<<<grid, 256>>>(A, Wt, bias, resid, Cf, Ch, M, N, K, gelu);
}
static inline void wtrans(const float* in, __half* out, int K, int N) {
    transpose_kernel<<<dim3(N / 32, K / 32), 256>>>(in, out, K, N);
}

extern "C" void kernel_launch(void* const* d_in, const int* in_sizes, int n_in,
                              void* d_out, int out_size) {
    const float* x    = (const float*)d_in[0];
    const float* ctx  = (const float*)d_in[1];
    const float* sq_w = (const float*)d_in[2];
    const float* sk_w = (const float*)d_in[3];
    const float* sv_w = (const float*)d_in[4];
    const float* so_w = (const float*)d_in[5];
    const float* so_b = (const float*)d_in[6];
    const float* cq_w = (const float*)d_in[7];
    const float* ck_w = (const float*)d_in[8];
    const float* cv_w = (const float*)d_in[9];
    const float* co_w = (const float*)d_in[10];
    const float* co_b = (const float*)d_in[11];
    const float* n1_g = (const float*)d_in[12];
    const float* n1_b = (const float*)d_in[13];
    const float* n2_g = (const float*)d_in[14];
    const float* n2_b = (const float*)d_in[15];
    const float* n3_g = (const float*)d_in[16];
    const float* n3_b = (const float*)d_in[17];
    const float* n4_g = (const float*)d_in[18];
    const float* n4_b = (const float*)d_in[19];
    const float* f1_w1 = (const float*)d_in[20];
    const float* f1_b1 = (const float*)d_in[21];
    const float* f1_w2 = (const float*)d_in[22];
    const float* f1_b2 = (const float*)d_in[23];
    const float* f2_w1 = (const float*)d_in[24];
    const float* f2_b1 = (const float*)d_in[25];
    const float* f2_w2 = (const float*)d_in[26];
    const float* f2_b2 = (const float*)d_in[27];
    float* out = (float*)d_out;

    float* px;
    __half *plnh, *pqkv, *pqh, *pckv, *pah, *phh, *pctxh, *pwt;
    cudaGetSymbolAddress((void**)&px, g_x);
    cudaGetSymbolAddress((void**)&plnh, g_ln_h);
    cudaGetSymbolAddress((void**)&pqkv, g_qkv_h);
    cudaGetSymbolAddress((void**)&pqh, g_q_h);
    cudaGetSymbolAddress((void**)&pckv, g_ckv_h);
    cudaGetSymbolAddress((void**)&pah, g_attn_h);
    cudaGetSymbolAddress((void**)&phh, g_hid_h);
    cudaGetSymbolAddress((void**)&pctxh, g_ctx_h);
    cudaGetSymbolAddress((void**)&pwt, g_wt);

    const int NCTX = BATCH * SC * CD;

    f2h_kernel<<<(NCTX + 255) / 256, 256>>>(ctx, pctxh, NCTX);
    wtrans(sq_w, pwt + WT_Q, H, H);
    wtrans(sk_w, pwt + WT_K, H, H);
    wtrans(sv_w, pwt + WT_V, H, H);
    wtrans(so_w, pwt + WT_O, H, H);
    wtrans(cq_w, pwt + WT_CQ, H, H);
    wtrans(co_w, pwt + WT_CO, H, H);
    wtrans(ck_w, pwt + WT_CK, CD, H);
    wtrans(cv_w, pwt + WT_CV, CD, H);
    wtrans(f1_w1, pwt + WT_F1A, H, FF);
    wtrans(f1_w2, pwt + WT_F1B, FF, H);
    wtrans(f2_w1, pwt + WT_F2A, H, FF);
    wtrans(f2_w2, pwt + WT_F2B, FF, H);

    // ---------------- Stage A: self-attention ----------------
    ln_kernel<<<BT, 256>>>(x, n1_g, n1_b, plnh);     // LN1 reads original x
    gemm(plnh, pwt + WT_Q, nullptr, nullptr, nullptr, pqkv, BT, 3 * H, H, 0); // fused QKV
    fattn_kernel<<<dim3(T / FA_BM, NH, BATCH), 128>>>(
        pqkv, 3 * H, pqkv + H, pqkv + 2 * H, 3 * H, pah, T);
    gemm(pah, pwt + WT_O, so_b, x, px, nullptr, BT, H, H, 0);  // resid = original x

    // ---------------- Stage B: FFN 1 ----------------
    ln_kernel<<<BT, 256>>>(px, n2_g, n2_b, plnh);
    gemm(plnh, pwt + WT_F1A, f1_b1, nullptr, nullptr, phh, BT, FF, H, 1);
    gemm(phh, pwt + WT_F1B, f1_b2, px, px, nullptr, BT, H, FF, 0);

    // ---------------- Stage C: cross-attention ----------------
    ln_kernel<<<BT, 256>>>(px, n3_g, n3_b, plnh);
    gemm(plnh, pwt + WT_CQ, nullptr, nullptr, nullptr, pqh, BT, H, H, 0);
    gemm(pctxh, pwt + WT_CK, nullptr, nullptr, nullptr, pckv, BATCH * SC, 2 * H, CD, 0); // fused cross K/V
    fattn_kernel<<<dim3(T / FA_BM, NH, BATCH), 128>>>(
        pqh, H, pckv, pckv + H, 2 * H, pah, SC);
    gemm(pah, pwt + WT_CO, co_b, px, px, nullptr, BT, H, H, 0);

    // ---------------- Stage D: FFN 2 ----------------
    ln_kernel<<<BT, 256>>>(px, n4_g, n4_b, plnh);
    gemm(plnh, pwt + WT_F2A, f2_b1, nullptr, nullptr, phh, BT, FF, H, 1);
    gemm(phh, pwt + WT_F2B, f2_b2, px, out, nullptr, BT, H, FF, 0);
}

// round 10
// speedup vs baseline: 1.4741x; 1.0557x over previous
#include <cuda_runtime.h>
#include <cuda_fp16.h>
#include <math.h>
#include <stddef.h>
#include <stdint.h>

// ---------------------------------------------------------------------------
// Problem dims
// ---------------------------------------------------------------------------
#define BATCH 4
#define T 1024
#define H 1024
#define NH 16
#define HD 64
#define CD 768
#define SC 77
#define FF 4096
#define BT (BATCH * T)

// ---------------------------------------------------------------------------
// Scratch
// ---------------------------------------------------------------------------
__device__ float g_x[BT * H];           // residual stream (fp32)
__device__ __half g_ln_h[BT * H];       // LN output (fp16)
__device__ __half g_qkv_h[BT * 3 * H];  // fused QKV (self)
__device__ __half g_q_h[BT * H];        // cross-attn Q
__device__ __half g_ckv_h[BATCH * SC * 2 * H]; // fused cross K/V
__device__ __half g_attn_h[BT * H];
__device__ __half g_hid_h[BT * FF];
__device__ __half g_ctx_h[BATCH * SC * CD];
// transposed fp16 weights, [N,K] row-major. Q,K,V contiguous; CK,CV contiguous.
#define WT_Q   0
#define WT_K   (WT_Q + H * H)
#define WT_V   (WT_K + H * H)
#define WT_O   (WT_V + H * H)
#define WT_CQ  (WT_O + H * H)
#define WT_CO  (WT_CQ + H * H)
#define WT_CK  (WT_CO + H * H)
#define WT_CV  (WT_CK + H * CD)
#define WT_F1A (WT_CV + H * CD)
#define WT_F1B (WT_F1A + FF * H)
#define WT_F2A (WT_F1B + H * FF)
#define WT_F2B (WT_F2A + FF * H)
#define WT_TOTAL (WT_F2B + H * FF)
__device__ __half g_wt[WT_TOTAL];

// ---------------------------------------------------------------------------
// Utility
// ---------------------------------------------------------------------------
__device__ __forceinline__ float warpSum(float v) {
#pragma unroll
    for (int o = 16; o; o >>= 1) v += __shfl_xor_sync(0xffffffffu, v, o);
    return v;
}
__device__ __forceinline__ uint32_t smem_u32(const void* p) {
    uint32_t a;
    asm("{ .reg .u64 t; cvta.to.shared.u64 t, %1; cvt.u32.u64 %0, t; }" : "=r"(a) : "l"(p));
    return a;
}
__device__ __forceinline__ void cp16(uint32_t saddr, const void* g, int srcBytes) {
    asm volatile("cp.async.cg.shared.global [%0], [%1], 16, %2;"
                 :: "r"(saddr), "l"(g), "r"(srcBytes) : "memory");
}
#define CP_COMMIT() asm volatile("cp.async.commit_group;" ::: "memory")
#define CP_WAITG1() asm volatile("cp.async.wait_group 1;" ::: "memory")
#define CP_WAIT0()  asm volatile("cp.async.wait_group 0;" ::: "memory")

__device__ __forceinline__ void mma_f16(float* c, const uint32_t* a, const uint32_t* b) {
    asm volatile(
        "mma.sync.aligned.m16n8k16.row.col.f32.f16.f16.f32 "
        "{%0,%1,%2,%3}, {%4,%5,%6,%7}, {%8,%9}, {%0,%1,%2,%3};"
        : "+f"(c[0]), "+f"(c[1]), "+f"(c[2]), "+f"(c[3])
        : "r"(a[0]), "r"(a[1]), "r"(a[2]), "r"(a[3]), "r"(b[0]), "r"(b[1]));
}
__device__ __forceinline__ void ldm_x4(uint32_t* r, uint32_t addr) {
    asm volatile("ldmatrix.sync.aligned.m8n8.x4.shared.b16 {%0,%1,%2,%3}, [%4];"
                 : "=r"(r[0]), "=r"(r[1]), "=r"(r[2]), "=r"(r[3]) : "r"(addr));
}
__device__ __forceinline__ void ldm_x4_t(uint32_t* r, uint32_t addr) {
    asm volatile("ldmatrix.sync.aligned.m8n8.x4.trans.shared.b16 {%0,%1,%2,%3}, [%4];"
                 : "=r"(r[0]), "=r"(r[1]), "=r"(r[2]), "=r"(r[3]) : "r"(addr));
}
__device__ __forceinline__ uint32_t h2exp2(uint32_t x) {
    uint32_t r; asm("ex2.approx.f16x2 %0, %1;" : "=r"(r) : "r"(x)); return r;
}

// ---------------------------------------------------------------------------
// Small kernels
// ---------------------------------------------------------------------------
__global__ void f2h_kernel(const float* __restrict__ in, __half* __restrict__ out, int n) {
    int i = blockIdx.x * blockDim.x + threadIdx.x;
    if (i < n) out[i] = __float2half(in[i]);
}

// Batched weight transpose + fp16: 12 weights, one launch.
#define NWT 12
struct WTParams {
    const float* src[NWT];
    __half* dst[NWT];
    int K[NWT], N[NWT], start[NWT];
};
__global__ void transpose_all_kernel(WTParams p) {
    __shared__ float tbuf[32][33];
    int bid = blockIdx.x;
    int wi = 0;
#pragma unroll
    for (int i = 1; i < NWT; i++) if (bid >= p.start[i]) wi = i;
    int tile = bid - p.start[wi];
    int K = p.K[wi], N = p.N[wi];
    int ntx = N >> 5;
    int n0 = (tile % ntx) << 5, k0 = (tile / ntx) << 5;
    const float* in = p.src[wi];
    __half* out = p.dst[wi];

    int tx = threadIdx.x & 31, ty = threadIdx.x >> 5;
#pragma unroll
    for (int i = 0; i < 32; i += 8)
        tbuf[ty + i][tx] = in[(size_t)(k0 + ty + i) * N + n0 + tx];
    __syncthreads();
#pragma unroll
    for (int i = 0; i < 32; i += 8)
        out[(size_t)(n0 + ty + i) * K + k0 + tx] = __float2half(tbuf[tx][ty + i]);
}

// ---------------------------------------------------------------------------
// LayerNorm: fp32 in -> fp16 out
// ---------------------------------------------------------------------------
__global__ void ln_kernel(const float* __restrict__ in,
                          const float* __restrict__ gamma,
                          const float* __restrict__ beta,
                          __half* __restrict__ out) {
    int row = blockIdx.x;
    int tid = threadIdx.x;
    float4 v = ((const float4*)(in + (size_t)row * H))[tid];

    float s = v.x + v.y + v.z + v.w;
    float s2 = v.x * v.x + v.y * v.y + v.z * v.z + v.w * v.w;
    __shared__ float sh_s[8], sh_s2[8];
    float ws = warpSum(s), ws2 = warpSum(s2);
    int wid = tid >> 5, lane = tid & 31;
    if (lane == 0) { sh_s[wid] = ws; sh_s2[wid] = ws2; }
    __syncthreads();
    float tot = 0.f, tot2 = 0.f;
#pragma unroll
    for (int w = 0; w < 8; w++) { tot += sh_s[w]; tot2 += sh_s2[w]; }
    float mean = tot * (1.0f / H);
    float var = tot2 * (1.0f / H) - mean * mean;
    float inv = rsqrtf(var + 1e-5f);

    float4 gm = ((const float4*)gamma)[tid];
    float4 bt = ((const float4*)beta)[tid];
    float o0 = (v.x - mean) * inv * gm.x + bt.x;
    float o1 = (v.y - mean) * inv * gm.y + bt.y;
    float o2 = (v.z - mean) * inv * gm.z + bt.z;
    float o3 = (v.w - mean) * inv * gm.w + bt.w;
    half2 h0 = __floats2half2_rn(o0, o1);
    half2 h1 = __floats2half2_rn(o2, o3);
    ((uint2*)(out + (size_t)row * H))[tid] = make_uint2(
        *(uint32_t*)&h0, *(uint32_t*)&h1);
}

// ---------------------------------------------------------------------------
// FP16 tensor-core GEMM, 3-stage cp.async pipeline, scalar fragment feed.
//   C[M,N] = A[M,K] @ Wt[N,K]^T (+bias)(+GELU)(+resid)
//   Dynamic SMEM: 3 stages x (A 10240 B + B 10240 B) = 61440 B.
// ---------------------------------------------------------------------------
#define KSTR 40
#define STG_HALVES (128 * KSTR)            // 5120 halves per operand tile
#define STAGE_HALVES (2 * STG_HALVES)      // A then B
#define GEMM_SMEM_BYTES (3 * STAGE_HALVES * 2)

__global__ __launch_bounds__(256, 2)
void gemm_h_kernel(const __half* __restrict__ A, const __half* __restrict__ Wt,
                   const float* __restrict__ bias, const float* __restrict__ resid,
                   float* __restrict__ Cf, __half* __restrict__ Ch,
                   int M, int N, int K, int do_gelu) {
    extern __shared__ __half smh[];

    int tid = threadIdx.x;
    int lane = tid & 31, w = tid >> 5;
    int g = lane >> 2, t = lane & 3;
    int wm = w & 3, wn = w >> 2;
    int row0 = blockIdx.y * 128;
    int col0 = blockIdx.x * 128;

    uint32_t smb = smem_u32(smh);

    int ldrow[2], ldc16[2];
#pragma unroll
    for (int i = 0; i < 2; i++) {
        int idx = i * 256 + tid;
        ldrow[i] = idx >> 2;
        ldc16[i] = idx & 3;
    }

    const int NK = K >> 5;

    // prologue: stages 0,1 as separate groups
#pragma unroll
    for (int st = 0; st < 2; st++) {
        int k0 = st << 5;
        uint32_t sa = smb + (st * STAGE_HALVES) * 2;
        uint32_t sb = sa + STG_HALVES * 2;
#pragma unroll
        for (int i = 0; i < 2; i++) {
            int r = ldrow[i], c16 = ldc16[i];
            int gr = row0 + r;
            const __half* ga = A + (size_t)(gr < M ? gr : row0) * K + k0 + c16 * 8;
            cp16(sa + (r * KSTR + c16 * 8) * 2, ga, gr < M ? 16 : 0);
            const __half* gb = Wt + (size_t)(col0 + r) * K + k0 + c16 * 8;
            cp16(sb + (r * KSTR + c16 * 8) * 2, gb, 16);
        }
        CP_COMMIT();
    }

    float c[2][8][4];
#pragma unroll
    for (int mt = 0; mt < 2; mt++)
#pragma unroll
        for (int nt = 0; nt < 8; nt++)
#pragma unroll
            for (int i = 0; i < 4; i++) c[mt][nt][i] = 0.f;

    int s = 0;   // stage of current compute
    for (int kt = 0; kt < NK; kt++) {
        // stage kt's group completes (two groups pending normally; last iter: one)
        if (kt == NK - 1) { CP_WAIT0(); } else { CP_WAITG1(); }
        __syncthreads();   // all threads see stage s; all readers of stage (kt+2)%3 done

        // issue loads for stage kt+2 (after the barrier -> race-free)
        if (kt + 2 < NK) {
            int sn = s + 2; if (sn >= 3) sn -= 3;
            int k0 = (kt + 2) << 5;
            uint32_t sa = smb + (sn * STAGE_HALVES) * 2;
            uint32_t sb = sa + STG_HALVES * 2;
#pragma unroll
            for (int i = 0; i < 2; i++) {
                int r = ldrow[i], c16 = ldc16[i];
                int gr = row0 + r;
                const __half* ga = A + (size_t)(gr < M ? gr : row0) * K + k0 + c16 * 8;
                cp16(sa + (r * KSTR + c16 * 8) * 2, ga, gr < M ? 16 : 0);
                const __half* gb = Wt + (size_t)(col0 + r) * K + k0 + c16 * 8;
                cp16(sb + (r * KSTR + c16 * 8) * 2, gb, 16);
            }
            CP_COMMIT();
        }

        const __half* as = smh + s * STAGE_HALVES;
        const __half* bs = as + STG_HALVES;
#pragma unroll
        for (int ks = 0; ks < 2; ks++) {
            int kb = ks * 16;
            uint32_t a[2][4], b[8][2];
#pragma unroll
            for (int mt = 0; mt < 2; mt++) {
                int m = wm * 32 + mt * 16 + g;
                a[mt][0] = *(const uint32_t*)(as + m * KSTR + kb + 2 * t);
                a[mt][1] = *(const uint32_t*)(as + (m + 8) * KSTR + kb + 2 * t);
                a[mt][2] = *(const uint32_t*)(as + m * KSTR + kb + 2 * t + 8);
                a[mt][3] = *(const uint32_t*)(as + (m + 8) * KSTR + kb + 2 * t + 8);
            }
#pragma unroll
            for (int nt = 0; nt < 8; nt++) {
                int n = wn * 64 + nt * 8 + g;
                b[nt][0] = *(const uint32_t*)(bs + n * KSTR + kb + 2 * t);
                b[nt][1] = *(const uint32_t*)(bs + n * KSTR + kb + 2 * t + 8);
            }
#pragma unroll
            for (int mt = 0; mt < 2; mt++)
#pragma unroll
                for (int nt = 0; nt < 8; nt++)
                    mma_f16(c[mt][nt], a[mt], b[nt]);
        }
        if (++s >= 3) s = 0;
    }

#pragma unroll
    for (int mt = 0; mt < 2; mt++) {
        int r = row0 + wm * 32 + mt * 16 + g;
#pragma unroll
        for (int nt = 0; nt < 8; nt++) {
            int cc = col0 + wn * 64 + nt * 8 + 2 * t;
            float v0 = c[mt][nt][0], v1 = c[mt][nt][1];
            float v2 = c[mt][nt][2], v3 = c[mt][nt][3];
            if (bias) {
                float b0 = bias[cc], b1 = bias[cc + 1];
                v0 += b0; v1 += b1; v2 += b0; v3 += b1;
            }
            if (do_gelu) {
                v0 = 0.5f * v0 * (1.0f + erff(v0 * 0.70710678118654752f));
                v1 = 0.5f * v1 * (1.0f + erff(v1 * 0.70710678118654752f));
                v2 = 0.5f * v2 * (1.0f + erff(v2 * 0.70710678118654752f));
                v3 = 0.5f * v3 * (1.0f + erff(v3 * 0.70710678118654752f));
            }
            if (r < M) {
                float o0 = v0, o1 = v1;
                if (resid) { o0 += resid[(size_t)r * N + cc]; o1 += resid[(size_t)r * N + cc + 1]; }
                if (Cf) { Cf[(size_t)r * N + cc] = o0; Cf[(size_t)r * N + cc + 1] = o1; }
                if (Ch) *(half2*)(Ch + (size_t)r * N + cc) = __floats2half2_rn(o0, o1);
            }
            if (r + 8 < M) {
                float o2 = v2, o3 = v3;
                if (resid) { o2 += resid[(size_t)(r + 8) * N + cc]; o3 += resid[(size_t)(r + 8) * N + cc + 1]; }
                if (Cf) { Cf[(size_t)(r + 8) * N + cc] = o2; Cf[(size_t)(r + 8) * N + cc + 1] = o3; }
                if (Ch) *(half2*)(Ch + (size_t)(r + 8) * N + cc) = __floats2half2_rn(o2, o3);
            }
        }
    }
}

// ---------------------------------------------------------------------------
// FP16 flash attention (strided Q and K/V for fused-QKV buffers).
// ---------------------------------------------------------------------------
#define FA_BM 64
#define FA_BN 64
#define FSTR 72
#define SCALE_L2E 0.18033688f   // 0.125 * log2(e)

__global__ __launch_bounds__(128)
void fattn_kernel(const __half* __restrict__ Qg, int QS,
                  const __half* __restrict__ Kg, const __half* __restrict__ Vg, int KS,
                  __half* __restrict__ Og, int Slen) {
    __shared__ __half sQ[FA_BM * FSTR];
    __shared__ __half sK[FA_BN * FSTR];
    __shared__ __half sV[FA_BN * FSTR];

    int b = blockIdx.z, h = blockIdx.y;
    int q0 = blockIdx.x * FA_BM;
    int tid = threadIdx.x, w = tid >> 5, lane = tid & 31;
    int g = lane >> 2, t = lane & 3;

    uint32_t sQb = smem_u32(sQ), sKb = smem_u32(sK), sVb = smem_u32(sV);

#pragma unroll
    for (int i = 0; i < 4; i++) {
        int idx = i * 128 + tid;
        int r = idx >> 3, c = (idx & 7) * 8;
        const __half* gp = Qg + (size_t)(b * T + q0 + r) * QS + h * HD + c;
        cp16(sQb + (r * FSTR + c) * 2, gp, 16);
    }
    CP_COMMIT();
    CP_WAIT0();
    __syncthreads();

    uint32_t aq[4][4];
    {
        int row = w * 16 + (lane & 7) + ((lane & 8) ? 8 : 0);
#pragma unroll
        for (int kt = 0; kt < 4; kt++) {
            int col = kt * 16 + ((lane & 16) ? 8 : 0);
            ldm_x4(aq[kt], sQb + (row * FSTR + col) * 2);
        }
    }

    float m0 = -1e30f, m1 = -1e30f, l0 = 0.f, l1 = 0.f;
    float o[8][4];
#pragma unroll
    for (int dt = 0; dt < 8; dt++)
#pragma unroll
        for (int i = 0; i < 4; i++) o[dt][i] = 0.f;

    for (int j0 = 0; j0 < Slen; j0 += FA_BN) {
        __syncthreads();
#pragma unroll
        for (int i = 0; i < 4; i++) {
            int idx = i * 128 + tid;
            int r = idx >> 3, c = (idx & 7) * 8;
            int j = j0 + r;
            int ok = (j < Slen) ? 16 : 0;
            size_t goff = (size_t)(b * Slen + (j < Slen ? j : 0)) * KS + h * HD + c;
            cp16(sKb + (r * FSTR + c) * 2, Kg + goff, ok);
            cp16(sVb + (r * FSTR + c) * 2, Vg + goff, ok);
        }
        CP_COMMIT();
        CP_WAIT0();
        __syncthreads();

        float c[8][4];
#pragma unroll
        for (int nt = 0; nt < 8; nt++)
#pragma unroll
            for (int i = 0; i < 4; i++) c[nt][i] = 0.f;

        {
            int krow = (lane & 7) + ((lane & 16) ? 8 : 0);
            int kcol = (lane & 8) ? 8 : 0;
#pragma unroll
            for (int kt = 0; kt < 4; kt++) {
#pragma unroll
                for (int nt2 = 0; nt2 < 4; nt2++) {
                    uint32_t bb[4];
                    ldm_x4(bb, sKb + ((nt2 * 16 + krow) * FSTR + kt * 16 + kcol) * 2);
                    mma_f16(c[nt2 * 2], aq[kt], bb);
                    mma_f16(c[nt2 * 2 + 1], aq[kt], bb + 2);
                }
            }
        }

#pragma unroll
        for (int nt = 0; nt < 8; nt++)
#pragma unroll
            for (int i = 0; i < 4; i++) c[nt][i] *= SCALE_L2E;
        if (j0 + FA_BN > Slen) {
#pragma unroll
            for (int nt = 0; nt < 8; nt++) {
                int ja = j0 + nt * 8 + 2 * t;
                if (ja >= Slen) { c[nt][0] = -1e30f; c[nt][2] = -1e30f; }
                if (ja + 1 >= Slen) { c[nt][1] = -1e30f; c[nt][3] = -1e30f; }
            }
        }

        float tm0 = -1e30f, tm1 = -1e30f;
#pragma unroll
        for (int nt = 0; nt < 8; nt++) {
            tm0 = fmaxf(tm0, fmaxf(c[nt][0], c[nt][1]));
            tm1 = fmaxf(tm1, fmaxf(c[nt][2], c[nt][3]));
        }
        tm0 = fmaxf(tm0, __shfl_xor_sync(0xffffffffu, tm0, 1));
        tm0 = fmaxf(tm0, __shfl_xor_sync(0xffffffffu, tm0, 2));
        tm1 = fmaxf(tm1, __shfl_xor_sync(0xffffffffu, tm1, 1));
        tm1 = fmaxf(tm1, __shfl_xor_sync(0xffffffffu, tm1, 2));

        float mn0 = fmaxf(m0, tm0), mn1 = fmaxf(m1, tm1);
        float al0 = exp2f(m0 - mn0), al1 = exp2f(m1 - mn1);
        m0 = mn0; m1 = mn1;

        uint32_t ph[8][2];
        float s0 = 0.f, s1 = 0.f;
#pragma unroll
        for (int nt = 0; nt < 8; nt++) {
            half2 x0 = __floats2half2_rn(c[nt][0] - mn0, c[nt][1] - mn0);
            half2 x1 = __floats2half2_rn(c[nt][2] - mn1, c[nt][3] - mn1);
            ph[nt][0] = h2exp2(*(uint32_t*)&x0);
            ph[nt][1] = h2exp2(*(uint32_t*)&x1);
            float2 f0 = __half22float2(*(half2*)&ph[nt][0]);
            float2 f1 = __half22float2(*(half2*)&ph[nt][1]);
            s0 += f0.x + f0.y;
            s1 += f1.x + f1.y;
        }
        s0 += __shfl_xor_sync(0xffffffffu, s0, 1);
        s0 += __shfl_xor_sync(0xffffffffu, s0, 2);
        s1 += __shfl_xor_sync(0xffffffffu, s1, 1);
        s1 += __shfl_xor_sync(0xffffffffu, s1, 2);
        l0 = l0 * al0 + s0;
        l1 = l1 * al1 + s1;

#pragma unroll
        for (int dt = 0; dt < 8; dt++) {
            o[dt][0] *= al0; o[dt][1] *= al0;
            o[dt][2] *= al1; o[dt][3] *= al1;
        }

        {
            int vrow = (lane & 7) + ((lane & 8) ? 8 : 0);
            int vcol = (lane & 16) ? 8 : 0;
#pragma unroll
            for (int kt = 0; kt < 4; kt++) {
                uint32_t af[4] = { ph[2 * kt][0], ph[2 * kt][1],
                                   ph[2 * kt + 1][0], ph[2 * kt + 1][1] };
#pragma unroll
                for (int dt2 = 0; dt2 < 4; dt2++) {
                    uint32_t bb[4];
                    ldm_x4_t(bb, sVb + ((kt * 16 + vrow) * FSTR + dt2 * 16 + vcol) * 2);
                    mma_f16(o[dt2 * 2], af, bb);
                    mma_f16(o[dt2 * 2 + 1], af, bb + 2);
                }
            }
        }
    }

    float inv0 = 1.0f / l0, inv1 = 1.0f / l1;
    int row0 = q0 + w * 16 + g;
#pragma unroll
    for (int dt = 0; dt < 8; dt++) {
        int col = dt * 8 + 2 * t;
        half2 h0 = __floats2half2_rn(o[dt][0] * inv0, o[dt][1] * inv0);
        half2 h1 = __floats2half2_rn(o[dt][2] * inv1, o[dt][3] * inv1);
        *(half2*)(Og + ((size_t)(b * T + row0) * H) + h * HD + col) = h0;
        *(half2*)(Og + ((size_t)(b * T + row0 + 8) * H) + h * HD + col) = h1;
    }
}

// ---------------------------------------------------------------------------
// Orchestration
// ---------------------------------------------------------------------------
static inline void gemm(const __half* A, const __half* Wt, const float* bias,
                        const float* resid, float* Cf, __half* Ch,
                        int M, int N, int K, int gelu) {
    dim3 grid(N / 128, (M + 127) / 128);
    gemm_h_kernel<<<grid, 256, GEMM_SMEM_BYTES>>>(A, Wt, bias, resid, Cf, Ch, M, N, K, gelu);
}

extern "C" void kernel_launch(void* const* d_in, const int* in_sizes, int n_in,
                              void* d_out, int out_size) {
    const float* x    = (const float*)d_in[0];
    const float* ctx  = (const float*)d_in[1];
    const float* sq_w = (const float*)d_in[2];
    const float* sk_w = (const float*)d_in[3];
    const float* sv_w = (const float*)d_in[4];
    const float* so_w = (const float*)d_in[5];
    const float* so_b = (const float*)d_in[6];
    const float* cq_w = (const float*)d_in[7];
    const float* ck_w = (const float*)d_in[8];
    const float* cv_w = (const float*)d_in[9];
    const float* co_w = (const float*)d_in[10];
    const float* co_b = (const float*)d_in[11];
    const float* n1_g = (const float*)d_in[12];
    const float* n1_b = (const float*)d_in[13];
    const float* n2_g = (const float*)d_in[14];
    const float* n2_b = (const float*)d_in[15];
    const float* n3_g = (const float*)d_in[16];
    const float* n3_b = (const float*)d_in[17];
    const float* n4_g = (const float*)d_in[18];
    const float* n4_b = (const float*)d_in[19];
    const float* f1_w1 = (const float*)d_in[20];
    const float* f1_b1 = (const float*)d_in[21];
    const float* f1_w2 = (const float*)d_in[22];
    const float* f1_b2 = (const float*)d_in[23];
    const float* f2_w1 = (const float*)d_in[24];
    const float* f2_b1 = (const float*)d_in[25];
    const float* f2_w2 = (const float*)d_in[26];
    const float* f2_b2 = (const float*)d_in[27];
    float* out = (float*)d_out;

    float* px;
    __half *plnh, *pqkv, *pqh, *pckv, *pah, *phh, *pctxh, *pwt;
    cudaGetSymbolAddress((void**)&px, g_x);
    cudaGetSymbolAddress((void**)&plnh, g_ln_h);
    cudaGetSymbolAddress((void**)&pqkv, g_qkv_h);
    cudaGetSymbolAddress((void**)&pqh, g_q_h);
    cudaGetSymbolAddress((void**)&pckv, g_ckv_h);
    cudaGetSymbolAddress((void**)&pah, g_attn_h);
    cudaGetSymbolAddress((void**)&phh, g_hid_h);
    cudaGetSymbolAddress((void**)&pctxh, g_ctx_h);
    cudaGetSymbolAddress((void**)&pwt, g_wt);

    cudaFuncSetAttribute(gemm_h_kernel, cudaFuncAttributeMaxDynamicSharedMemorySize,
                         GEMM_SMEM_BYTES);

    const int NCTX = BATCH * SC * CD;

    f2h_kernel<<<(NCTX + 255) / 256, 256>>>(ctx, pctxh, NCTX);

    // batched weight transpose: one launch for all 12 weights
    {
        WTParams p;
        const float* srcs[NWT] = { sq_w, sk_w, sv_w, so_w, cq_w, co_w,
                                   ck_w, cv_w, f1_w1, f1_w2, f2_w1, f2_w2 };
        __half* dsts[NWT] = { pwt + WT_Q, pwt + WT_K, pwt + WT_V, pwt + WT_O,
                              pwt + WT_CQ, pwt + WT_CO, pwt + WT_CK, pwt + WT_CV,
                              pwt + WT_F1A, pwt + WT_F1B, pwt + WT_F2A, pwt + WT_F2B };
        int Ks[NWT] = { H, H, H, H, H, H, CD, CD, H, FF, H, FF };
        int Ns[NWT] = { H, H, H, H, H, H, H, H, FF, H, FF, H };
        int acc = 0;
        for (int i = 0; i < NWT; i++) {
            p.src[i] = srcs[i]; p.dst[i] = dsts[i];
            p.K[i] = Ks[i]; p.N[i] = Ns[i];
            p.start[i] = acc;
            acc += (Ks[i] / 32) * (Ns[i] / 32);
        }
        transpose_all_kernel<<<acc, 256>>>(p);
    }

    // ---------------- Stage A: self-attention ----------------
    ln_kernel<<<BT, 256>>>(x, n1_g, n1_b, plnh);
    gemm(plnh, pwt + WT_Q, nullptr, nullptr, nullptr, pqkv, BT, 3 * H, H, 0);
    fattn_kernel<<<dim3(T / FA_BM, NH, BATCH), 128>>>(
        pqkv, 3 * H, pqkv + H, pqkv + 2 * H, 3 * H, pah, T);
    gemm(pah, pwt + WT_O, so_b, x, px, nullptr, BT, H, H, 0);

    // ---------------- Stage B: FFN 1 ----------------
    ln_kernel<<<BT, 256>>>(px, n2_g, n2_b, plnh);
    gemm(plnh, pwt + WT_F1A, f1_b1, nullptr, nullptr, phh, BT, FF, H, 1);
    gemm(phh, pwt + WT_F1B, f1_b2, px, px, nullptr, BT, H, FF, 0);

    // ---------------- Stage C: cross-attention ----------------
    ln_kernel<<<BT, 256>>>(px, n3_g, n3_b, plnh);
    gemm(plnh, pwt + WT_CQ, nullptr, nullptr, nullptr, pqh, BT, H, H, 0);
    gemm(pctxh, pwt + WT_CK, nullptr, nullptr, nullptr, pckv, BATCH * SC, 2 * H, CD, 0);
    fattn_kernel<<<dim3(T / FA_BM, NH, BATCH), 128>>>(
        pqh, H, pckv, pckv + H, 2 * H, pah, SC);
    gemm(pah, pwt + WT_CO, co_b, px, px, nullptr, BT, H, H, 0);

    // ---------------- Stage D: FFN 2 ----------------
    ln_kernel<<<BT, 256>>>(px, n4_g, n4_b, plnh);
    gemm(plnh, pwt + WT_F2A, f2_b1, nullptr, nullptr, phh, BT, FF, H, 1);
    gemm(phh, pwt + WT_F2B, f2_b2, px, out, nullptr, BT, H, FF, 0);
}

// round 11
// speedup vs baseline: 1.6040x; 1.0881x over previous
#include <cuda_runtime.h>
#include <cuda_fp16.h>
#include <math.h>
#include <stddef.h>
#include <stdint.h>

// ---------------------------------------------------------------------------
// Problem dims
// ---------------------------------------------------------------------------
#define BATCH 4
#define T 1024
#define H 1024
#define NH 16
#define HD 64
#define CD 768
#define SC 77
#define FF 4096
#define BT (BATCH * T)

// ---------------------------------------------------------------------------
// Scratch
// ---------------------------------------------------------------------------
__device__ float g_x[BT * H];
__device__ __half g_ln_h[BT * H];
__device__ __half g_qkv_h[BT * 3 * H];
__device__ __half g_q_h[BT * H];
__device__ __half g_ckv_h[BATCH * SC * 2 * H];
__device__ __half g_attn_h[BT * H];
__device__ __half g_hid_h[BT * FF];
__device__ __half g_ctx_h[BATCH * SC * CD];
#define WT_Q   0
#define WT_K   (WT_Q + H * H)
#define WT_V   (WT_K + H * H)
#define WT_O   (WT_V + H * H)
#define WT_CQ  (WT_O + H * H)
#define WT_CO  (WT_CQ + H * H)
#define WT_CK  (WT_CO + H * H)
#define WT_CV  (WT_CK + H * CD)
#define WT_F1A (WT_CV + H * CD)
#define WT_F1B (WT_F1A + FF * H)
#define WT_F2A (WT_F1B + H * FF)
#define WT_F2B (WT_F2A + FF * H)
#define WT_TOTAL (WT_F2B + H * FF)
__device__ __half g_wt[WT_TOTAL];

// ---------------------------------------------------------------------------
// Utility
// ---------------------------------------------------------------------------
__device__ __forceinline__ float warpSum(float v) {
#pragma unroll
    for (int o = 16; o; o >>= 1) v += __shfl_xor_sync(0xffffffffu, v, o);
    return v;
}
__device__ __forceinline__ uint32_t smem_u32(const void* p) {
    uint32_t a;
    asm("{ .reg .u64 t; cvta.to.shared.u64 t, %1; cvt.u32.u64 %0, t; }" : "=r"(a) : "l"(p));
    return a;
}
__device__ __forceinline__ void cp16(uint32_t saddr, const void* g, int srcBytes) {
    asm volatile("cp.async.cg.shared.global [%0], [%1], 16, %2;"
                 :: "r"(saddr), "l"(g), "r"(srcBytes) : "memory");
}
#define CP_COMMIT() asm volatile("cp.async.commit_group;" ::: "memory")
#define CP_WAITG1() asm volatile("cp.async.wait_group 1;" ::: "memory")
#define CP_WAIT0()  asm volatile("cp.async.wait_group 0;" ::: "memory")

__device__ __forceinline__ void mma_f16(float* c, const uint32_t* a, const uint32_t* b) {
    asm volatile(
        "mma.sync.aligned.m16n8k16.row.col.f32.f16.f16.f32 "
        "{%0,%1,%2,%3}, {%4,%5,%6,%7}, {%8,%9}, {%0,%1,%2,%3};"
        : "+f"(c[0]), "+f"(c[1]), "+f"(c[2]), "+f"(c[3])
        : "r"(a[0]), "r"(a[1]), "r"(a[2]), "r"(a[3]), "r"(b[0]), "r"(b[1]));
}
__device__ __forceinline__ void ldm_x4(uint32_t* r, uint32_t addr) {
    asm volatile("ldmatrix.sync.aligned.m8n8.x4.shared.b16 {%0,%1,%2,%3}, [%4];"
                 : "=r"(r[0]), "=r"(r[1]), "=r"(r[2]), "=r"(r[3]) : "r"(addr));
}
__device__ __forceinline__ void ldm_x4_t(uint32_t* r, uint32_t addr) {
    asm volatile("ldmatrix.sync.aligned.m8n8.x4.trans.shared.b16 {%0,%1,%2,%3}, [%4];"
                 : "=r"(r[0]), "=r"(r[1]), "=r"(r[2]), "=r"(r[3]) : "r"(addr));
}
__device__ __forceinline__ uint32_t h2exp2(uint32_t x) {
    uint32_t r; asm("ex2.approx.f16x2 %0, %1;" : "=r"(r) : "r"(x)); return r;
}

// ---------------------------------------------------------------------------
// Small kernels
// ---------------------------------------------------------------------------
__global__ void f2h_kernel(const float* __restrict__ in, __half* __restrict__ out, int n) {
    int i = blockIdx.x * blockDim.x + threadIdx.x;
    if (i < n) out[i] = __float2half(in[i]);
}

#define NWT 12
struct WTParams {
    const float* src[NWT];
    __half* dst[NWT];
    int K[NWT], N[NWT], start[NWT];
};
__global__ void transpose_all_kernel(WTParams p) {
    __shared__ float tbuf[32][33];
    int bid = blockIdx.x;
    int wi = 0;
#pragma unroll
    for (int i = 1; i < NWT; i++) if (bid >= p.start[i]) wi = i;
    int tile = bid - p.start[wi];
    int K = p.K[wi], N = p.N[wi];
    int ntx = N >> 5;
    int n0 = (tile % ntx) << 5, k0 = (tile / ntx) << 5;
    const float* in = p.src[wi];
    __half* out = p.dst[wi];

    int tx = threadIdx.x & 31, ty = threadIdx.x >> 5;
#pragma unroll
    for (int i = 0; i < 32; i += 8)
        tbuf[ty + i][tx] = in[(size_t)(k0 + ty + i) * N + n0 + tx];
    __syncthreads();
#pragma unroll
    for (int i = 0; i < 32; i += 8)
        out[(size_t)(n0 + ty + i) * K + k0 + tx] = __float2half(tbuf[tx][ty + i]);
}

// ---------------------------------------------------------------------------
// LayerNorm: warp-per-row (8 rows/block), no block-level reduction.
// ---------------------------------------------------------------------------
__global__ void ln_kernel(const float* __restrict__ in,
                          const float* __restrict__ gamma,
                          const float* __restrict__ beta,
                          __half* __restrict__ out) {
    int row = blockIdx.x * 8 + (threadIdx.x >> 5);
    int lane = threadIdx.x & 31;
    const float4* r4 = (const float4*)(in + (size_t)row * H);

    float4 v[8];
    float s = 0.f, s2 = 0.f;
#pragma unroll
    for (int j = 0; j < 8; j++) {
        v[j] = r4[lane + 32 * j];
        s += v[j].x + v[j].y + v[j].z + v[j].w;
        s2 += v[j].x * v[j].x + v[j].y * v[j].y + v[j].z * v[j].z + v[j].w * v[j].w;
    }
    s = warpSum(s); s2 = warpSum(s2);
    float mean = s * (1.0f / H);
    float var = s2 * (1.0f / H) - mean * mean;
    float inv = rsqrtf(var + 1e-5f);

    uint2* o2 = (uint2*)(out + (size_t)row * H);
#pragma unroll
    for (int j = 0; j < 8; j++) {
        float4 gm = ((const float4*)gamma)[lane + 32 * j];
        float4 bt = ((const float4*)beta)[lane + 32 * j];
        float o0 = (v[j].x - mean) * inv * gm.x + bt.x;
        float o1 = (v[j].y - mean) * inv * gm.y + bt.y;
        float o2v = (v[j].z - mean) * inv * gm.z + bt.z;
        float o3 = (v[j].w - mean) * inv * gm.w + bt.w;
        half2 h0 = __floats2half2_rn(o0, o1);
        half2 h1 = __floats2half2_rn(o2v, o3);
        o2[lane + 32 * j] = make_uint2(*(uint32_t*)&h0, *(uint32_t*)&h1);
    }
}

// ---------------------------------------------------------------------------
// FP16 tensor-core GEMM, BK=64, 3-stage cp.async pipeline, scalar frag feed.
//   C[M,N] = A[M,K] @ Wt[N,K]^T (+bias)(+GELU)(+resid)
//   SMEM: 3 stages x (A 18432 B + B 18432 B) = 110592 B.
// ---------------------------------------------------------------------------
#define KSTR 72
#define STG_HALVES (128 * KSTR)            // 9216 halves per operand tile
#define STAGE_HALVES (2 * STG_HALVES)
#define GEMM_SMEM_BYTES (3 * STAGE_HALVES * 2)

__global__ __launch_bounds__(256, 2)
void gemm_h_kernel(const __half* __restrict__ A, const __half* __restrict__ Wt,
                   const float* __restrict__ bias, const float* __restrict__ resid,
                   float* __restrict__ Cf, __half* __restrict__ Ch,
                   int M, int N, int K, int do_gelu) {
    extern __shared__ __half smh[];

    int tid = threadIdx.x;
    int lane = tid & 31, w = tid >> 5;
    int g = lane >> 2, t = lane & 3;
    int wm = w & 3, wn = w >> 2;
    int row0 = blockIdx.y * 128;
    int col0 = blockIdx.x * 128;

    uint32_t smb = smem_u32(smh);

    // loader: per operand 128 rows x 8 chunks of 16B; 4 chunks/thread
    int ldrow[4], ldc16[4];
#pragma unroll
    for (int i = 0; i < 4; i++) {
        int idx = i * 256 + tid;
        ldrow[i] = idx >> 3;
        ldc16[i] = idx & 7;
    }

    const int NK = K >> 6;

    // prologue: stages 0,1
#pragma unroll
    for (int st = 0; st < 2; st++) {
        int k0 = st << 6;
        uint32_t sa = smb + (st * STAGE_HALVES) * 2;
        uint32_t sb = sa + STG_HALVES * 2;
#pragma unroll
        for (int i = 0; i < 4; i++) {
            int r = ldrow[i], c16 = ldc16[i];
            int gr = row0 + r;
            const __half* ga = A + (size_t)(gr < M ? gr : row0) * K + k0 + c16 * 8;
            cp16(sa + (r * KSTR + c16 * 8) * 2, ga, gr < M ? 16 : 0);
            const __half* gb = Wt + (size_t)(col0 + r) * K + k0 + c16 * 8;
            cp16(sb + (r * KSTR + c16 * 8) * 2, gb, 16);
        }
        CP_COMMIT();
    }

    float c[2][8][4];
#pragma unroll
    for (int mt = 0; mt < 2; mt++)
#pragma unroll
        for (int nt = 0; nt < 8; nt++)
#pragma unroll
            for (int i = 0; i < 4; i++) c[mt][nt][i] = 0.f;

    int s = 0;
    for (int kt = 0; kt < NK; kt++) {
        if (kt == NK - 1) { CP_WAIT0(); } else { CP_WAITG1(); }
        __syncthreads();

        if (kt + 2 < NK) {
            int sn = s + 2; if (sn >= 3) sn -= 3;
            int k0 = (kt + 2) << 6;
            uint32_t sa = smb + (sn * STAGE_HALVES) * 2;
            uint32_t sb = sa + STG_HALVES * 2;
#pragma unroll
            for (int i = 0; i < 4; i++) {
                int r = ldrow[i], c16 = ldc16[i];
                int gr = row0 + r;
                const __half* ga = A + (size_t)(gr < M ? gr : row0) * K + k0 + c16 * 8;
                cp16(sa + (r * KSTR + c16 * 8) * 2, ga, gr < M ? 16 : 0);
                const __half* gb = Wt + (size_t)(col0 + r) * K + k0 + c16 * 8;
                cp16(sb + (r * KSTR + c16 * 8) * 2, gb, 16);
            }
            CP_COMMIT();
        }

        const __half* as = smh + s * STAGE_HALVES;
        const __half* bs = as + STG_HALVES;
#pragma unroll
        for (int ks = 0; ks < 4; ks++) {
            int kb = ks * 16;
            uint32_t a[2][4], b[8][2];
#pragma unroll
            for (int mt = 0; mt < 2; mt++) {
                int m = wm * 32 + mt * 16 + g;
                a[mt][0] = *(const uint32_t*)(as + m * KSTR + kb + 2 * t);
                a[mt][1] = *(const uint32_t*)(as + (m + 8) * KSTR + kb + 2 * t);
                a[mt][2] = *(const uint32_t*)(as + m * KSTR + kb + 2 * t + 8);
                a[mt][3] = *(const uint32_t*)(as + (m + 8) * KSTR + kb + 2 * t + 8);
            }
#pragma unroll
            for (int nt = 0; nt < 8; nt++) {
                int n = wn * 64 + nt * 8 + g;
                b[nt][0] = *(const uint32_t*)(bs + n * KSTR + kb + 2 * t);
                b[nt][1] = *(const uint32_t*)(bs + n * KSTR + kb + 2 * t + 8);
            }
#pragma unroll
            for (int mt = 0; mt < 2; mt++)
#pragma unroll
                for (int nt = 0; nt < 8; nt++)
                    mma_f16(c[mt][nt], a[mt], b[nt]);
        }
        if (++s >= 3) s = 0;
    }

#pragma unroll
    for (int mt = 0; mt < 2; mt++) {
        int r = row0 + wm * 32 + mt * 16 + g;
#pragma unroll
        for (int nt = 0; nt < 8; nt++) {
            int cc = col0 + wn * 64 + nt * 8 + 2 * t;
            float v0 = c[mt][nt][0], v1 = c[mt][nt][1];
            float v2 = c[mt][nt][2], v3 = c[mt][nt][3];
            if (bias) {
                float b0 = bias[cc], b1 = bias[cc + 1];
                v0 += b0; v1 += b1; v2 += b0; v3 += b1;
            }
            if (do_gelu) {
                v0 = 0.5f * v0 * (1.0f + erff(v0 * 0.70710678118654752f));
                v1 = 0.5f * v1 * (1.0f + erff(v1 * 0.70710678118654752f));
                v2 = 0.5f * v2 * (1.0f + erff(v2 * 0.70710678118654752f));
                v3 = 0.5f * v3 * (1.0f + erff(v3 * 0.70710678118654752f));
            }
            if (r < M) {
                float o0 = v0, o1 = v1;
                if (resid) { o0 += resid[(size_t)r * N + cc]; o1 += resid[(size_t)r * N + cc + 1]; }
                if (Cf) { Cf[(size_t)r * N + cc] = o0; Cf[(size_t)r * N + cc + 1] = o1; }
                if (Ch) *(half2*)(Ch + (size_t)r * N + cc) = __floats2half2_rn(o0, o1);
            }
            if (r + 8 < M) {
                float o2 = v2, o3 = v3;
                if (resid) { o2 += resid[(size_t)(r + 8) * N + cc]; o3 += resid[(size_t)(r + 8) * N + cc + 1]; }
                if (Cf) { Cf[(size_t)(r + 8) * N + cc] = o2; Cf[(size_t)(r + 8) * N + cc + 1] = o3; }
                if (Ch) *(half2*)(Ch + (size_t)(r + 8) * N + cc) = __floats2half2_rn(o2, o3);
            }
        }
    }
}

// ---------------------------------------------------------------------------
// FP16 flash attention (strided Q and K/V for fused-QKV buffers).
// ---------------------------------------------------------------------------
#define FA_BM 64
#define FA_BN 64
#define FSTR 72
#define SCALE_L2E 0.18033688f   // 0.125 * log2(e)

__global__ __launch_bounds__(128)
void fattn_kernel(const __half* __restrict__ Qg, int QS,
                  const __half* __restrict__ Kg, const __half* __restrict__ Vg, int KS,
                  __half* __restrict__ Og, int Slen) {
    __shared__ __half sQ[FA_BM * FSTR];
    __shared__ __half sK[FA_BN * FSTR];
    __shared__ __half sV[FA_BN * FSTR];

    int b = blockIdx.z, h = blockIdx.y;
    int q0 = blockIdx.x * FA_BM;
    int tid = threadIdx.x, w = tid >> 5, lane = tid & 31;
    int g = lane >> 2, t = lane & 3;

    uint32_t sQb = smem_u32(sQ), sKb = smem_u32(sK), sVb = smem_u32(sV);

#pragma unroll
    for (int i = 0; i < 4; i++) {
        int idx = i * 128 + tid;
        int r = idx >> 3, c = (idx & 7) * 8;
        const __half* gp = Qg + (size_t)(b * T + q0 + r) * QS + h * HD + c;
        cp16(sQb + (r * FSTR + c) * 2, gp, 16);
    }
    CP_COMMIT();
    CP_WAIT0();
    __syncthreads();

    uint32_t aq[4][4];
    {
        int row = w * 16 + (lane & 7) + ((lane & 8) ? 8 : 0);
#pragma unroll
        for (int kt = 0; kt < 4; kt++) {
            int col = kt * 16 + ((lane & 16) ? 8 : 0);
            ldm_x4(aq[kt], sQb + (row * FSTR + col) * 2);
        }
    }

    float m0 = -1e30f, m1 = -1e30f, l0 = 0.f, l1 = 0.f;
    float o[8][4];
#pragma unroll
    for (int dt = 0; dt < 8; dt++)
#pragma unroll
        for (int i = 0; i < 4; i++) o[dt][i] = 0.f;

    for (int j0 = 0; j0 < Slen; j0 += FA_BN) {
        __syncthreads();
#pragma unroll
        for (int i = 0; i < 4; i++) {
            int idx = i * 128 + tid;
            int r = idx >> 3, c = (idx & 7) * 8;
            int j = j0 + r;
            int ok = (j < Slen) ? 16 : 0;
            size_t goff = (size_t)(b * Slen + (j < Slen ? j : 0)) * KS + h * HD + c;
            cp16(sKb + (r * FSTR + c) * 2, Kg + goff, ok);
            cp16(sVb + (r * FSTR + c) * 2, Vg + goff, ok);
        }
        CP_COMMIT();
        CP_WAIT0();
        __syncthreads();

        float c[8][4];
#pragma unroll
        for (int nt = 0; nt < 8; nt++)
#pragma unroll
            for (int i = 0; i < 4; i++) c[nt][i] = 0.f;

        {
            int krow = (lane & 7) + ((lane & 16) ? 8 : 0);
            int kcol = (lane & 8) ? 8 : 0;
#pragma unroll
            for (int kt = 0; kt < 4; kt++) {
#pragma unroll
                for (int nt2 = 0; nt2 < 4; nt2++) {
                    uint32_t bb[4];
                    ldm_x4(bb, sKb + ((nt2 * 16 + krow) * FSTR + kt * 16 + kcol) * 2);
                    mma_f16(c[nt2 * 2], aq[kt], bb);
                    mma_f16(c[nt2 * 2 + 1], aq[kt], bb + 2);
                }
            }
        }

#pragma unroll
        for (int nt = 0; nt < 8; nt++)
#pragma unroll
            for (int i = 0; i < 4; i++) c[nt][i] *= SCALE_L2E;
        if (j0 + FA_BN > Slen) {
#pragma unroll
            for (int nt = 0; nt < 8; nt++) {
                int ja = j0 + nt * 8 + 2 * t;
                if (ja >= Slen) { c[nt][0] = -1e30f; c[nt][2] = -1e30f; }
                if (ja + 1 >= Slen) { c[nt][1] = -1e30f; c[nt][3] = -1e30f; }
            }
        }

        float tm0 = -1e30f, tm1 = -1e30f;
#pragma unroll
        for (int nt = 0; nt < 8; nt++) {
            tm0 = fmaxf(tm0, fmaxf(c[nt][0], c[nt][1]));
            tm1 = fmaxf(tm1, fmaxf(c[nt][2], c[nt][3]));
        }
        tm0 = fmaxf(tm0, __shfl_xor_sync(0xffffffffu, tm0, 1));
        tm0 = fmaxf(tm0, __shfl_xor_sync(0xffffffffu, tm0, 2));
        tm1 = fmaxf(tm1, __shfl_xor_sync(0xffffffffu, tm1, 1));
        tm1 = fmaxf(tm1, __shfl_xor_sync(0xffffffffu, tm1, 2));

        float mn0 = fmaxf(m0, tm0), mn1 = fmaxf(m1, tm1);
        float al0 = exp2f(m0 - mn0), al1 = exp2f(m1 - mn1);
        m0 = mn0; m1 = mn1;

        uint32_t ph[8][2];
        float s0 = 0.f, s1 = 0.f;
#pragma unroll
        for (int nt = 0; nt < 8; nt++) {
            half2 x0 = __floats2half2_rn(c[nt][0] - mn0, c[nt][1] - mn0);
            half2 x1 = __floats2half2_rn(c[nt][2] - mn1, c[nt][3] - mn1);
            ph[nt][0] = h2exp2(*(uint32_t*)&x0);
            ph[nt][1] = h2exp2(*(uint32_t*)&x1);
            float2 f0 = __half22float2(*(half2*)&ph[nt][0]);
            float2 f1 = __half22float2(*(half2*)&ph[nt][1]);
            s0 += f0.x + f0.y;
            s1 += f1.x + f1.y;
        }
        s0 += __shfl_xor_sync(0xffffffffu, s0, 1);
        s0 += __shfl_xor_sync(0xffffffffu, s0, 2);
        s1 += __shfl_xor_sync(0xffffffffu, s1, 1);
        s1 += __shfl_xor_sync(0xffffffffu, s1, 2);
        l0 = l0 * al0 + s0;
        l1 = l1 * al1 + s1;

#pragma unroll
        for (int dt = 0; dt < 8; dt++) {
            o[dt][0] *= al0; o[dt][1] *= al0;
            o[dt][2] *= al1; o[dt][3] *= al1;
        }

        {
            int vrow = (lane & 7) + ((lane & 8) ? 8 : 0);
            int vcol = (lane & 16) ? 8 : 0;
#pragma unroll
            for (int kt = 0; kt < 4; kt++) {
                uint32_t af[4] = { ph[2 * kt][0], ph[2 * kt][1],
                                   ph[2 * kt + 1][0], ph[2 * kt + 1][1] };
#pragma unroll
                for (int dt2 = 0; dt2 < 4; dt2++) {
                    uint32_t bb[4];
                    ldm_x4_t(bb, sVb + ((kt * 16 + vrow) * FSTR + dt2 * 16 + vcol) * 2);
                    mma_f16(o[dt2 * 2], af, bb);
                    mma_f16(o[dt2 * 2 + 1], af, bb + 2);
                }
            }
        }
    }

    float inv0 = 1.0f / l0, inv1 = 1.0f / l1;
    int row0 = q0 + w * 16 + g;
#pragma unroll
    for (int dt = 0; dt < 8; dt++) {
        int col = dt * 8 + 2 * t;
        half2 h0 = __floats2half2_rn(o[dt][0] * inv0, o[dt][1] * inv0);
        half2 h1 = __floats2half2_rn(o[dt][2] * inv1, o[dt][3] * inv1);
        *(half2*)(Og + ((size_t)(b * T + row0) * H) + h * HD + col) = h0;
        *(half2*)(Og + ((size_t)(b * T + row0 + 8) * H) + h * HD + col) = h1;
    }
}

// ---------------------------------------------------------------------------
// Orchestration
// ---------------------------------------------------------------------------
static inline void gemm(const __half* A, const __half* Wt, const float* bias,
                        const float* resid, float* Cf, __half* Ch,
                        int M, int N, int K, int gelu) {
    dim3 grid(N / 128, (M + 127) / 128);
    gemm_h_kernel<<<grid, 256, GEMM_SMEM_BYTES>>>(A, Wt, bias, resid, Cf, Ch, M, N, K, gelu);
}

extern "C" void kernel_launch(void* const* d_in, const int* in_sizes, int n_in,
                              void* d_out, int out_size) {
    const float* x    = (const float*)d_in[0];
    const float* ctx  = (const float*)d_in[1];
    const float* sq_w = (const float*)d_in[2];
    const float* sk_w = (const float*)d_in[3];
    const float* sv_w = (const float*)d_in[4];
    const float* so_w = (const float*)d_in[5];
    const float* so_b = (const float*)d_in[6];
    const float* cq_w = (const float*)d_in[7];
    const float* ck_w = (const float*)d_in[8];
    const float* cv_w = (const float*)d_in[9];
    const float* co_w = (const float*)d_in[10];
    const float* co_b = (const float*)d_in[11];
    const float* n1_g = (const float*)d_in[12];
    const float* n1_b = (const float*)d_in[13];
    const float* n2_g = (const float*)d_in[14];
    const float* n2_b = (const float*)d_in[15];
    const float* n3_g = (const float*)d_in[16];
    const float* n3_b = (const float*)d_in[17];
    const float* n4_g = (const float*)d_in[18];
    const float* n4_b = (const float*)d_in[19];
    const float* f1_w1 = (const float*)d_in[20];
    const float* f1_b1 = (const float*)d_in[21];
    const float* f1_w2 = (const float*)d_in[22];
    const float* f1_b2 = (const float*)d_in[23];
    const float* f2_w1 = (const float*)d_in[24];
    const float* f2_b1 = (const float*)d_in[25];
    const float* f2_w2 = (const float*)d_in[26];
    const float* f2_b2 = (const float*)d_in[27];
    float* out = (float*)d_out;

    float* px;
    __half *plnh, *pqkv, *pqh, *pckv, *pah, *phh, *pctxh, *pwt;
    cudaGetSymbolAddress((void**)&px, g_x);
    cudaGetSymbolAddress((void**)&plnh, g_ln_h);
    cudaGetSymbolAddress((void**)&pqkv, g_qkv_h);
    cudaGetSymbolAddress((void**)&pqh, g_q_h);
    cudaGetSymbolAddress((void**)&pckv, g_ckv_h);
    cudaGetSymbolAddress((void**)&pah, g_attn_h);
    cudaGetSymbolAddress((void**)&phh, g_hid_h);
    cudaGetSymbolAddress((void**)&pctxh, g_ctx_h);
    cudaGetSymbolAddress((void**)&pwt, g_wt);

    cudaFuncSetAttribute(gemm_h_kernel, cudaFuncAttributeMaxDynamicSharedMemorySize,
                         GEMM_SMEM_BYTES);

    const int NCTX = BATCH * SC * CD;

    f2h_kernel<<<(NCTX + 255) / 256, 256>>>(ctx, pctxh, NCTX);

    // batched weight transpose: one launch for all 12 weights
    {
        WTParams p;
        const float* srcs[NWT] = { sq_w, sk_w, sv_w, so_w, cq_w, co_w,
                                   ck_w, cv_w, f1_w1, f1_w2, f2_w1, f2_w2 };
        __half* dsts[NWT] = { pwt + WT_Q, pwt + WT_K, pwt + WT_V, pwt + WT_O,
                              pwt + WT_CQ, pwt + WT_CO, pwt + WT_CK, pwt + WT_CV,
                              pwt + WT_F1A, pwt + WT_F1B, pwt + WT_F2A, pwt + WT_F2B };
        int Ks[NWT] = { H, H, H, H, H, H, CD, CD, H, FF, H, FF };
        int Ns[NWT] = { H, H, H, H, H, H, H, H, FF, H, FF, H };
        int acc = 0;
        for (int i = 0; i < NWT; i++) {
            p.src[i] = srcs[i]; p.dst[i] = dsts[i];
            p.K[i] = Ks[i]; p.N[i] = Ns[i];
            p.start[i] = acc;
            acc += (Ks[i] / 32) * (Ns[i] / 32);
        }
        transpose_all_kernel<<<acc, 256>>>(p);
    }

    // ---------------- Stage A: self-attention ----------------
    ln_kernel<<<BT / 8, 256>>>(x, n1_g, n1_b, plnh);
    gemm(plnh, pwt + WT_Q, nullptr, nullptr, nullptr, pqkv, BT, 3 * H, H, 0);
    fattn_kernel<<<dim3(T / FA_BM, NH, BATCH), 128>>>(
        pqkv, 3 * H, pqkv + H, pqkv + 2 * H, 3 * H, pah, T);
    gemm(pah, pwt + WT_O, so_b, x, px, nullptr, BT, H, H, 0);

    // ---------------- Stage B: FFN 1 ----------------
    ln_kernel<<<BT / 8, 256>>>(px, n2_g, n2_b, plnh);
    gemm(plnh, pwt + WT_F1A, f1_b1, nullptr, nullptr, phh, BT, FF, H, 1);
    gemm(phh, pwt + WT_F1B, f1_b2, px, px, nullptr, BT, H, FF, 0);

    // ---------------- Stage C: cross-attention ----------------
    ln_kernel<<<BT / 8, 256>>>(px, n3_g, n3_b, plnh);
    gemm(plnh, pwt + WT_CQ, nullptr, nullptr, nullptr, pqh, BT, H, H, 0);
    gemm(pctxh, pwt + WT_CK, nullptr, nullptr, nullptr, pckv, BATCH * SC, 2 * H, CD, 0);
    fattn_kernel<<<dim3(T / FA_BM, NH, BATCH), 128>>>(
        pqh, H, pckv, pckv + H, 2 * H, pah, SC);
    gemm(pah, pwt + WT_CO, co_b, px, px, nullptr, BT, H, H, 0);

    // ---------------- Stage D: FFN 2 ----------------
    ln_kernel<<<BT / 8, 256>>>(px, n4_g, n4_b, plnh);
    gemm(plnh, pwt + WT_F2A, f2_b1, nullptr, nullptr, phh, BT, FF, H, 1);
    gemm(phh, pwt + WT_F2B, f2_b2, px, out, nullptr, BT, H, FF, 0);
}